// round 11
// baseline (speedup 1.0000x reference)
#include <cuda_runtime.h>
#include <cstdint>

#define B_SZ   64
#define H_SZ   256
#define G_SZ   768            // 3*H
#define T_ENC  48
#define T_DEC  32
#define V_OUT  32000
#define M_ENC  (B_SZ * T_ENC) // 3072
#define M_DEC  (B_SZ * T_DEC) // 2048
#define M_ALL  (M_ENC + M_DEC)// 5120

// gru: 32 clusters x 4 CTAs, 64 ch per CTA, 2 batches per cluster
#define GR_RANKS 4
#define GR_BPC   2
#define GR_CTAS  128
#define GR_SMEM_BYTES (256 * 65 * 4)         // wn per-thread rows, 66560

// f16 mma tiles: 128x128, k-chunk 64, 3-stage cp.async
#define LT_A_BYTES 16384
#define LT_STAGE   32768
#define LT_SMEM    (3 * LT_STAGE)            // 98304

// ---------------- device scratch ----------------
__device__ float g_xg_enc[M_ENC * G_SZ];
__device__ float g_xg_dec[M_DEC * G_SZ];
__device__ __align__(16) unsigned short g_a_h[M_ALL * H_SZ];      // gathered emb fp16
__device__ __align__(16) unsigned short g_wih_h[2 * G_SZ * H_SZ]; // fp16 Wih (enc,dec)
__device__ __align__(16) unsigned short g_dech_h[M_DEC * H_SZ];   // fp16 dec hidden
__device__ __align__(16) unsigned short g_fcw_h[V_OUT * H_SZ];    // fp16 fc_W

// ---------------- helpers ----------------
__device__ __forceinline__ void fma2(unsigned long long& d,
                                     unsigned long long a, unsigned long long b) {
    asm("fma.rn.f32x2 %0, %1, %2, %0;" : "+l"(d) : "l"(a), "l"(b));
}
__device__ __forceinline__ unsigned long long add2(unsigned long long a,
                                                   unsigned long long b) {
    unsigned long long d;
    asm("add.rn.f32x2 %0, %1, %2;" : "=l"(d) : "l"(a), "l"(b));
    return d;
}
__device__ __forceinline__ void unpack2(unsigned long long v, float& lo, float& hi) {
    asm("mov.b64 {%0,%1}, %2;" : "=f"(lo), "=f"(hi) : "l"(v));
}
__device__ __forceinline__ unsigned long long dup2(float w) {
    unsigned long long d;
    asm("mov.b64 %0, {%1,%1};" : "=l"(d) : "f"(w));
    return d;
}
__device__ __forceinline__ unsigned long long pack64(float lo, float hi) {
    unsigned long long d;
    asm("mov.b64 %0, {%1,%2};" : "=l"(d) : "f"(lo), "f"(hi));
    return d;
}
__device__ __forceinline__ unsigned long long shfl_xor64(unsigned long long v, int m) {
    unsigned lo = (unsigned)v, hi = (unsigned)(v >> 32);
    lo = __shfl_xor_sync(0xFFFFFFFFu, lo, m);
    hi = __shfl_xor_sync(0xFFFFFFFFu, hi, m);
    return ((unsigned long long)hi << 32) | lo;
}
__device__ __forceinline__ unsigned smem_u32(const void* p) {
    unsigned a;
    asm("{ .reg .u64 t; cvta.to.shared.u64 t, %1; cvt.u32.u64 %0, t; }"
        : "=r"(a) : "l"(p));
    return a;
}
__device__ __forceinline__ unsigned short f2h(float x) {
    unsigned short h;
    asm("cvt.rn.f16.f32 %0, %1;" : "=h"(h) : "f"(x));
    return h;
}
__device__ __forceinline__ unsigned pack_h2(float lo, float hi) {
    unsigned r;
    asm("cvt.rn.f16x2.f32 %0, %1, %2;" : "=r"(r) : "f"(hi), "f"(lo));
    return r;
}
__device__ __forceinline__ void mma_f16(float* d,
                                        unsigned a0, unsigned a1, unsigned a2, unsigned a3,
                                        unsigned b0, unsigned b1) {
    asm volatile(
        "mma.sync.aligned.m16n8k16.row.col.f32.f16.f16.f32 "
        "{%0,%1,%2,%3}, {%4,%5,%6,%7}, {%8,%9}, {%0,%1,%2,%3};"
        : "+f"(d[0]), "+f"(d[1]), "+f"(d[2]), "+f"(d[3])
        : "r"(a0), "r"(a1), "r"(a2), "r"(a3), "r"(b0), "r"(b1));
}

#define LDSM_X4(r0, r1, r2, r3, a) \
    asm volatile("ldmatrix.sync.aligned.m8n8.x4.shared.b16 {%0,%1,%2,%3}, [%4];" \
                 : "=r"(r0), "=r"(r1), "=r"(r2), "=r"(r3) : "r"(a))

#define CP_ASYNC16(dst, src) \
    asm volatile("cp.async.cg.shared.global [%0], [%1], 16;" \
                 :: "r"(dst), "l"(src) : "memory")

#define MBAR_INIT(addr, cnt) \
    asm volatile("mbarrier.init.shared.b64 [%0], %1;" :: "r"(addr), "r"(cnt) : "memory")

#define MBAR_EXPECT(addr, bytes) \
    asm volatile("mbarrier.arrive.expect_tx.shared.b64 _, [%0], %1;" \
                 :: "r"(addr), "r"(bytes) : "memory")

#define MBAR_WAIT(addr, parity) do {                                          \
    unsigned _mb = (addr), _ph = (unsigned)(parity);                          \
    asm volatile("{\n\t.reg .pred P;\n\t"                                     \
        "WL_%=:\n\t"                                                          \
        "mbarrier.try_wait.parity.acquire.cta.shared::cta.b64 P, [%0], %1, 0x989680;\n\t" \
        "@P bra.uni WD_%=;\n\t"                                               \
        "bra.uni WL_%=;\n\t"                                                  \
        "WD_%=:\n\t}" :: "r"(_mb), "r"(_ph) : "memory");                      \
} while (0)

// ---------------- kernel 0a: fc_W fp32 -> fp16 ----------------
__global__ void __launch_bounds__(256) cvt_w(const float* __restrict__ fcW) {
    long i = ((long)blockIdx.x * 256 + threadIdx.x) * 8;
    float4 v0 = *(const float4*)(fcW + i);
    float4 v1 = *(const float4*)(fcW + i + 4);
    uint4 o;
    o.x = pack_h2(v0.x, v0.y); o.y = pack_h2(v0.z, v0.w);
    o.z = pack_h2(v1.x, v1.y); o.w = pack_h2(v1.z, v1.w);
    *(uint4*)(g_fcw_h + i) = o;
}

// ---------------- kernel 0b: Wih (enc+dec) fp32 -> fp16 ----------------
__global__ void __launch_bounds__(256) cvt_wih(const float* __restrict__ encW,
                                               const float* __restrict__ decW) {
    long idx = (long)blockIdx.x * 256 + threadIdx.x;   // 49152 threads
    long i = idx * 8;
    const long half = (long)G_SZ * H_SZ;               // 196608
    const float* s = (i < half) ? (encW + i) : (decW + i - half);
    float4 v0 = *(const float4*)s;
    float4 v1 = *(const float4*)(s + 4);
    uint4 o;
    o.x = pack_h2(v0.x, v0.y); o.y = pack_h2(v0.z, v0.w);
    o.z = pack_h2(v1.x, v1.y); o.w = pack_h2(v1.z, v1.w);
    *(uint4*)(g_wih_h + i) = o;
}

// ---------------- kernel 0c: gather emb rows -> dense fp16 A --------------
__global__ void __launch_bounds__(256) gather_a(
    const float* __restrict__ enc_emb, const float* __restrict__ dec_emb,
    const int* __restrict__ src, const int* __restrict__ trg)
{
    int idx = blockIdx.x * 256 + threadIdx.x;   // 163840 threads
    int gm = idx >> 5;
    int q  = idx & 31;                          // 8-float chunk within row
    const float* emb;
    int tok;
    if (gm < M_ENC) {
        tok = src[gm];
        emb = enc_emb;
    } else {
        int g2 = gm - M_ENC;
        int t = g2 & 31, b = g2 >> 5;
        tok = (t == 0) ? 1 : trg[b * T_DEC + t - 1];
        emb = dec_emb;
    }
    const float* s = emb + (long)tok * H_SZ + q * 8;
    float4 v0 = *(const float4*)s;
    float4 v1 = *(const float4*)(s + 4);
    uint4 o;
    o.x = pack_h2(v0.x, v0.y); o.y = pack_h2(v0.z, v0.w);
    o.z = pack_h2(v1.x, v1.y); o.w = pack_h2(v1.z, v1.w);
    *(uint4*)(g_a_h + (long)gm * H_SZ + q * 8) = o;
}

// ---------------- kernel 1: xg via fp16 mma (128x128 tile) -----------------
__global__ void __launch_bounds__(128, 2) xg_f16(
    const float* __restrict__ enc_bih, const float* __restrict__ dec_bih)
{
    extern __shared__ __align__(16) char smc[];
    const unsigned sb = smem_u32(smc);
    const int tid = threadIdx.x;
    const int warp = tid >> 5, lane = tid & 31;
    const int group = lane >> 2, tig = lane & 3;
    const int m_blk = blockIdx.x * 128;
    const int n_blk = blockIdx.y * 128;
    const int m_w = (warp >> 1) * 64;
    const int n_w = (warp & 1) * 64;
    const bool enc = (m_blk < M_ENC);
    const unsigned short* wih = g_wih_h + (enc ? 0 : (long)G_SZ * H_SZ);
    const float* bias = enc ? enc_bih : dec_bih;

    // per-thread row pointers (8 A rows, 8 B rows)
    const unsigned short* arow[8];
    const unsigned short* brow[8];
    int us[8];
#pragma unroll
    for (int i = 0; i < 8; i++) {
        int f = i * 128 + tid;
        int r = f >> 3;
        us[i] = f & 7;
        arow[i] = g_a_h + (long)(m_blk + r) * H_SZ;
        brow[i] = wih + (long)(n_blk + r) * H_SZ;
    }

#define XG_ISSUE(c_, s_) do {                                                 \
    unsigned ab_ = sb + (s_) * LT_STAGE;                                      \
    unsigned bb_ = ab_ + LT_A_BYTES;                                          \
    _Pragma("unroll")                                                         \
    for (int i_ = 0; i_ < 8; i_++) {                                          \
        int f_ = i_ * 128 + tid;                                              \
        int r_ = f_ >> 3, u_ = us[i_];                                        \
        unsigned d_ = ab_ + r_ * 128 + ((u_ ^ (r_ & 7)) << 4);                \
        CP_ASYNC16(d_, arow[i_] + (c_) * 64 + u_ * 8);                        \
    }                                                                         \
    _Pragma("unroll")                                                         \
    for (int i_ = 0; i_ < 8; i_++) {                                          \
        int f_ = i_ * 128 + tid;                                              \
        int r_ = f_ >> 3, u_ = us[i_];                                        \
        unsigned d_ = bb_ + r_ * 128 + ((u_ ^ (r_ & 7)) << 4);                \
        CP_ASYNC16(d_, brow[i_] + (c_) * 64 + u_ * 8);                        \
    }                                                                         \
    asm volatile("cp.async.commit_group;" ::: "memory");                      \
} while (0)

    float acc[4][8][4];
#pragma unroll
    for (int i = 0; i < 4; i++)
#pragma unroll
        for (int jn = 0; jn < 8; jn++)
#pragma unroll
            for (int k = 0; k < 4; k++) acc[i][jn][k] = 0.f;

    XG_ISSUE(0, 0);
    XG_ISSUE(1, 1);
    XG_ISSUE(2, 2);

    const int a_row0 = m_w + ((lane >> 3) & 1) * 8 + (lane & 7);
    const int a_usel = lane >> 4;
    const int b_row0 = n_w + (lane & 7);
    const int b_usel = lane >> 3;

#pragma unroll
    for (int c = 0; c < 4; c++) {
        if (c == 0 || c == 1) asm volatile("cp.async.wait_group 2;" ::: "memory");
        else if (c == 2)      asm volatile("cp.async.wait_group 1;" ::: "memory");
        else                  asm volatile("cp.async.wait_group 0;" ::: "memory");
        __syncthreads();

        unsigned ab = sb + (c % 3) * LT_STAGE;
        unsigned bb = ab + LT_A_BYTES;

        unsigned bf[8][4];
#pragma unroll
        for (int ks = 0; ks < 4; ks++) {
            if ((ks & 1) == 0) {
                const int p = ks >> 1;
#pragma unroll
                for (int ni = 0; ni < 8; ni++) {
                    int row = b_row0 + ni * 8;
                    int u = 4 * p + b_usel;
                    unsigned addr = bb + row * 128 + ((u ^ (row & 7)) << 4);
                    LDSM_X4(bf[ni][0], bf[ni][1], bf[ni][2], bf[ni][3], addr);
                }
            }
            unsigned af[4][4];
#pragma unroll
            for (int mi = 0; mi < 4; mi++) {
                int row = a_row0 + mi * 16;
                int u = 2 * ks + a_usel;
                unsigned addr = ab + row * 128 + ((u ^ (row & 7)) << 4);
                LDSM_X4(af[mi][0], af[mi][1], af[mi][2], af[mi][3], addr);
            }
            const int h = (ks & 1) * 2;
#pragma unroll
            for (int mi = 0; mi < 4; mi++)
#pragma unroll
                for (int ni = 0; ni < 8; ni++)
                    mma_f16(acc[mi][ni], af[mi][0], af[mi][1], af[mi][2], af[mi][3],
                            bf[ni][h], bf[ni][h + 1]);
        }
        __syncthreads();
        if (c == 0) XG_ISSUE(3, 0);
    }

    // epilogue -> fp32 xg with bias
    float* xout = enc ? (g_xg_enc + (long)m_blk * G_SZ)
                      : (g_xg_dec + (long)(m_blk - M_ENC) * G_SZ);
#pragma unroll
    for (int mi = 0; mi < 4; mi++) {
        int rm0 = m_w + mi * 16 + group;
#pragma unroll
        for (int ni = 0; ni < 8; ni++) {
            int gn = n_blk + n_w + ni * 8 + tig * 2;
            float2 bbv = *(const float2*)(bias + gn);
            float2 o0, o1;
            o0.x = acc[mi][ni][0] + bbv.x; o0.y = acc[mi][ni][1] + bbv.y;
            o1.x = acc[mi][ni][2] + bbv.x; o1.y = acc[mi][ni][3] + bbv.y;
            *(float2*)(xout + (long)rm0 * G_SZ + gn)       = o0;
            *(float2*)(xout + (long)(rm0 + 8) * G_SZ + gn) = o1;
        }
    }
#undef XG_ISSUE
}

// ---------------- kernel 2: cluster GRU v6 ---------------------------------
// Thread (j = tid>>2, ksl = tid&3). wr/wz register-resident (full unroll),
// wn in per-thread smem rows (stride 65 -> conflict-free). fma2 dot, butterfly
// shuffle reduction (no redm, no per-step __syncthreads). st.async exchange.
__global__ void __launch_bounds__(256)
__cluster_dims__(GR_RANKS, 1, 1)
gru_rec(const float* __restrict__ encWhh, const float* __restrict__ encBhh,
        const float* __restrict__ decWhh, const float* __restrict__ decBhh)
{
    extern __shared__ __align__(16) float wn_s[];    // [256][65]
    __shared__ __align__(16) float h_s[2 * 512];     // [buf][k=256][b=2]
    __shared__ __align__(16) unsigned long long h_mb[2];

    const int tid  = threadIdx.x;
    const int j    = tid >> 2;   // channel within CTA (0..63)
    const int ksl  = tid & 3;    // k-slice (64 k each)
    const int rank = blockIdx.x & (GR_RANKS - 1);
    const int cid  = blockIdx.x >> 2;

    for (int i = tid; i < 1024; i += 256) h_s[i] = 0.f;
    if (tid == 0) {
        MBAR_INIT(smem_u32(&h_mb[0]), 1);
        MBAR_INIT(smem_u32(&h_mb[1]), 1);
        MBAR_EXPECT(smem_u32(&h_mb[0]), 2048u);
        MBAR_EXPECT(smem_u32(&h_mb[1]), 2048u);
    }
    __syncthreads();
    asm volatile("barrier.cluster.arrive.aligned;" ::: "memory");
    asm volatile("barrier.cluster.wait.aligned;" ::: "memory");

    const bool lead = (ksl == 0);
    const int cg  = rank * 64 + j;
    const unsigned h_base = smem_u32(h_s);
    const unsigned mb_base = smem_u32(&h_mb[0]);
    float* wn = wn_s + tid * 65;

    int buf = 0;
    int par0 = 0, par1 = 0;
    bool first = true;
    for (int ph = 0; ph < 2; ph++) {
        const int T = ph ? T_DEC : T_ENC;
        const float* xg  = ph ? g_xg_dec : g_xg_enc;
        const float* Bhh = ph ? decBhh : encBhh;
        const float* Wp  = ph ? decWhh : encWhh;

        // r,z weights -> registers; n weights -> own smem row (stride 65)
        float wr[64], wz[64];
        {
            const float* pr = Wp + (long)(0 * H_SZ + cg) * H_SZ + ksl * 64;
            const float* pz = Wp + (long)(1 * H_SZ + cg) * H_SZ + ksl * 64;
            const float* pn = Wp + (long)(2 * H_SZ + cg) * H_SZ + ksl * 64;
#pragma unroll
            for (int q = 0; q < 16; q++) {
                float4 a = __ldg((const float4*)(pr + q * 4));
                wr[q*4+0]=a.x; wr[q*4+1]=a.y; wr[q*4+2]=a.z; wr[q*4+3]=a.w;
                float4 b = __ldg((const float4*)(pz + q * 4));
                wz[q*4+0]=b.x; wz[q*4+1]=b.y; wz[q*4+2]=b.z; wz[q*4+3]=b.w;
                float4 c = __ldg((const float4*)(pn + q * 4));
                wn[q*4+0]=c.x; wn[q*4+1]=c.y; wn[q*4+2]=c.z; wn[q*4+3]=c.w;
            }
        }
        float br = 0.f, bz = 0.f, bn = 0.f;
        if (lead) {
            br = __ldg(Bhh + cg);
            bz = __ldg(Bhh + H_SZ + cg);
            bn = __ldg(Bhh + 2 * H_SZ + cg);
        }

        for (int t = 0; t < T; t++) {
            if (!first) {
                unsigned mb = mb_base + buf * 8;
                int par = buf ? par1 : par0;
                MBAR_WAIT(mb, par);
                if (buf) par1 ^= 1; else par0 ^= 1;
                if (tid == 0) MBAR_EXPECT(mb, 2048u);
            }
            first = false;

            float xr[2], xz[2], xn[2];
            if (lead) {
#pragma unroll
                for (int b = 0; b < 2; b++) {
                    const int bg = cid * GR_BPC + b;
                    const float* xp = xg + (long)(bg * T + t) * G_SZ + cg;
                    xr[b] = __ldg(xp); xz[b] = __ldg(xp + H_SZ); xn[b] = __ldg(xp + 2 * H_SZ);
                }
            }

            // fma2 dot over this thread's 64-k slice (both batches packed)
            unsigned long long a0 = 0ull, a1 = 0ull, a2 = 0ull;
            const float* hb = h_s + buf * 512 + ksl * 128;
#pragma unroll
            for (int kk = 0; kk < 64; kk++) {
                unsigned long long hv = *(const unsigned long long*)(hb + kk * 2);
                fma2(a0, hv, dup2(wr[kk]));
                fma2(a1, hv, dup2(wz[kk]));
                fma2(a2, hv, dup2(wn[kk]));
            }
            // butterfly reduce across the 4 ksl lanes (adjacent lanes)
            a0 = add2(a0, shfl_xor64(a0, 1)); a0 = add2(a0, shfl_xor64(a0, 2));
            a1 = add2(a1, shfl_xor64(a1, 1)); a1 = add2(a1, shfl_xor64(a1, 2));
            a2 = add2(a2, shfl_xor64(a2, 1)); a2 = add2(a2, shfl_xor64(a2, 2));

            if (lead) {
                float sr0, sr1, sz0, sz1, sn0, sn1;
                unpack2(a0, sr0, sr1);
                unpack2(a1, sz0, sz1);
                unpack2(a2, sn0, sn1);
                float hnew[2];
                {
                    float hold = h_s[buf * 512 + cg * 2 + 0];
                    float r = 1.f / (1.f + __expf(-(xr[0] + sr0 + br)));
                    float z = 1.f / (1.f + __expf(-(xz[0] + sz0 + bz)));
                    float n = tanhf(xn[0] + r * (sn0 + bn));
                    hnew[0] = (1.f - z) * n + z * hold;
                }
                {
                    float hold = h_s[buf * 512 + cg * 2 + 1];
                    float r = 1.f / (1.f + __expf(-(xr[1] + sr1 + br)));
                    float z = 1.f / (1.f + __expf(-(xz[1] + sz1 + bz)));
                    float n = tanhf(xn[1] + r * (sn1 + bn));
                    hnew[1] = (1.f - z) * n + z * hold;
                }

                const int nb = buf ^ 1;
                unsigned long long hp = pack64(hnew[0], hnew[1]);
                unsigned laddr = h_base + (unsigned)((nb * 512 + cg * 2) * 4);
                unsigned lmb   = mb_base + nb * 8;
#pragma unroll
                for (int rr = 0; rr < GR_RANKS; rr++) {
                    unsigned ra, rm;
                    asm volatile("mapa.shared::cluster.u32 %0, %1, %2;"
                                 : "=r"(ra) : "r"(laddr), "r"(rr));
                    asm volatile("mapa.shared::cluster.u32 %0, %1, %2;"
                                 : "=r"(rm) : "r"(lmb), "r"(rr));
                    asm volatile(
                        "st.async.shared::cluster.mbarrier::complete_tx::bytes.b64 [%0], %1, [%2];"
                        :: "r"(ra), "l"(hp), "r"(rm) : "memory");
                }
                if (ph) {
#pragma unroll
                    for (int b = 0; b < 2; b++) {
                        const int bg = cid * GR_BPC + b;
                        g_dech_h[(long)(bg * T_DEC + t) * H_SZ + cg] = f2h(hnew[b]);
                    }
                }
            }
            buf ^= 1;
        }
    }
    {
        unsigned mb = mb_base + buf * 8;
        int par = buf ? par1 : par0;
        MBAR_WAIT(mb, par);
    }
    asm volatile("barrier.cluster.arrive.aligned;" ::: "memory");
    asm volatile("barrier.cluster.wait.aligned;" ::: "memory");
}

// ---------------- kernel 3: logits, 4 warps x 64x64, 3-stage cp.async ------
__global__ void __launch_bounds__(128, 2) logits_f16(
    const float* __restrict__ fcb, float* __restrict__ out)
{
    extern __shared__ __align__(16) char smc[];
    const unsigned sb = smem_u32(smc);
    const int tid = threadIdx.x;
    const int warp = tid >> 5, lane = tid & 31;
    const int group = lane >> 2, tig = lane & 3;
    const int m_blk = blockIdx.x * 128;
    const int n_blk = blockIdx.y * 128;
    const int m_w = (warp >> 1) * 64;
    const int n_w = (warp & 1) * 64;

#define LT_ISSUE(c_, s_) do {                                                 \
    unsigned ab_ = sb + (s_) * LT_STAGE;                                      \
    unsigned bb_ = ab_ + LT_A_BYTES;                                          \
    _Pragma("unroll")                                                         \
    for (int i_ = 0; i_ < 8; i_++) {                                          \
        int f_ = i_ * 128 + tid;                                              \
        int r_ = f_ >> 3, u_ = f_ & 7;                                        \
        unsigned d_ = ab_ + r_ * 128 + ((u_ ^ (r_ & 7)) << 4);                \
        const void* s2_ = g_dech_h + (long)(m_blk + r_) * 256 + (c_) * 64 + u_ * 8; \
        CP_ASYNC16(d_, s2_);                                                  \
    }                                                                         \
    _Pragma("unroll")                                                         \
    for (int i_ = 0; i_ < 8; i_++) {                                          \
        int f_ = i_ * 128 + tid;                                              \
        int r_ = f_ >> 3, u_ = f_ & 7;                                        \
        unsigned d_ = bb_ + r_ * 128 + ((u_ ^ (r_ & 7)) << 4);                \
        const void* s2_ = g_fcw_h + (long)(n_blk + r_) * 256 + (c_) * 64 + u_ * 8; \
        CP_ASYNC16(d_, s2_);                                                  \
    }                                                                         \
    asm volatile("cp.async.commit_group;" ::: "memory");                      \
} while (0)

    float acc[4][8][4];
#pragma unroll
    for (int i = 0; i < 4; i++)
#pragma unroll
        for (int jn = 0; jn < 8; jn++)
#pragma unroll
            for (int k = 0; k < 4; k++) acc[i][jn][k] = 0.f;

    LT_ISSUE(0, 0);
    LT_ISSUE(1, 1);
    LT_ISSUE(2, 2);

    const int a_row0 = m_w + ((lane >> 3) & 1) * 8 + (lane & 7);
    const int a_usel = lane >> 4;
    const int b_row0 = n_w + (lane & 7);
    const int b_usel = lane >> 3;

#pragma unroll
    for (int c = 0; c < 4; c++) {
        if (c == 0 || c == 1) asm volatile("cp.async.wait_group 2;" ::: "memory");
        else if (c == 2)      asm volatile("cp.async.wait_group 1;" ::: "memory");
        else                  asm volatile("cp.async.wait_group 0;" ::: "memory");
        __syncthreads();

        unsigned ab = sb + (c % 3) * LT_STAGE;
        unsigned bb = ab + LT_A_BYTES;

        unsigned bf[8][4];
#pragma unroll
        for (int ks = 0; ks < 4; ks++) {
            if ((ks & 1) == 0) {
                const int p = ks >> 1;
#pragma unroll
                for (int ni = 0; ni < 8; ni++) {
                    int row = b_row0 + ni * 8;
                    int u = 4 * p + b_usel;
                    unsigned addr = bb + row * 128 + ((u ^ (row & 7)) << 4);
                    LDSM_X4(bf[ni][0], bf[ni][1], bf[ni][2], bf[ni][3], addr);
                }
            }
            unsigned af[4][4];
#pragma unroll
            for (int mi = 0; mi < 4; mi++) {
                int row = a_row0 + mi * 16;
                int u = 2 * ks + a_usel;
                unsigned addr = ab + row * 128 + ((u ^ (row & 7)) << 4);
                LDSM_X4(af[mi][0], af[mi][1], af[mi][2], af[mi][3], addr);
            }
            const int h = (ks & 1) * 2;
#pragma unroll
            for (int mi = 0; mi < 4; mi++)
#pragma unroll
                for (int ni = 0; ni < 8; ni++)
                    mma_f16(acc[mi][ni], af[mi][0], af[mi][1], af[mi][2], af[mi][3],
                            bf[ni][h], bf[ni][h + 1]);
        }
        __syncthreads();
        if (c == 0) LT_ISSUE(3, 0);
    }

#pragma unroll
    for (int mi = 0; mi < 4; mi++) {
        int gm0 = m_blk + m_w + mi * 16 + group;
#pragma unroll
        for (int ni = 0; ni < 8; ni++) {
            int gn = n_blk + n_w + ni * 8 + tig * 2;
            float2 bbv = *(const float2*)(fcb + gn);
            float2 o0, o1;
            o0.x = acc[mi][ni][0] + bbv.x; o0.y = acc[mi][ni][1] + bbv.y;
            o1.x = acc[mi][ni][2] + bbv.x; o1.y = acc[mi][ni][3] + bbv.y;
            *(float2*)(out + (long)gm0 * V_OUT + gn)       = o0;
            *(float2*)(out + (long)(gm0 + 8) * V_OUT + gn) = o1;
        }
    }
#undef LT_ISSUE
}

// ---------------- launch ----------------
extern "C" void kernel_launch(void* const* d_in, const int* in_sizes, int n_in,
                              void* d_out, int out_size) {
    const int*   src     = (const int*)  d_in[0];
    const int*   trg     = (const int*)  d_in[1];
    const float* enc_emb = (const float*)d_in[2];
    const float* enc_Wih = (const float*)d_in[3];
    const float* enc_Whh = (const float*)d_in[4];
    const float* enc_bih = (const float*)d_in[5];
    const float* enc_bhh = (const float*)d_in[6];
    const float* dec_emb = (const float*)d_in[7];
    const float* dec_Wih = (const float*)d_in[8];
    const float* dec_Whh = (const float*)d_in[9];
    const float* dec_bih = (const float*)d_in[10];
    const float* dec_bhh = (const float*)d_in[11];
    const float* fc_W    = (const float*)d_in[12];
    const float* fc_b    = (const float*)d_in[13];
    float* out = (float*)d_out;

    static bool attr_done = false;
    if (!attr_done) {
        cudaFuncSetAttribute((const void*)gru_rec,
                             cudaFuncAttributeMaxDynamicSharedMemorySize,
                             GR_SMEM_BYTES);
        cudaFuncSetAttribute((const void*)logits_f16,
                             cudaFuncAttributeMaxDynamicSharedMemorySize,
                             LT_SMEM);
        cudaFuncSetAttribute((const void*)xg_f16,
                             cudaFuncAttributeMaxDynamicSharedMemorySize,
                             LT_SMEM);
        attr_done = true;
    }

    cvt_w<<<V_OUT * H_SZ / (256 * 8), 256>>>(fc_W);
    cvt_wih<<<2 * G_SZ * H_SZ / (256 * 8), 256>>>(enc_Wih, dec_Wih);
    gather_a<<<M_ALL * 32 / 256, 256>>>(enc_emb, dec_emb, src, trg);
    xg_f16<<<dim3(M_ALL / 128, G_SZ / 128), 128, LT_SMEM>>>(enc_bih, dec_bih);
    gru_rec<<<GR_CTAS, 256, GR_SMEM_BYTES>>>(enc_Whh, enc_bhh, dec_Whh, dec_bhh);
    logits_f16<<<dim3(M_DEC / 128, V_OUT / 128), 128, LT_SMEM>>>(fc_b, out);
}

// round 12
// speedup vs baseline: 1.3434x; 1.3434x over previous
#include <cuda_runtime.h>
#include <cstdint>

#define B_SZ   64
#define H_SZ   256
#define G_SZ   768            // 3*H
#define T_ENC  48
#define T_DEC  32
#define V_OUT  32000
#define M_ENC  (B_SZ * T_ENC) // 3072
#define M_DEC  (B_SZ * T_DEC) // 2048
#define M_ALL  (M_ENC + M_DEC)// 5120

// gru: 32 clusters x 4 CTAs, 64 ch per CTA, 2 batches per cluster
#define GR_RANKS 4
#define GR_BPC   2
#define GR_CTAS  128
#define GR_WN_FLOATS (64 * 257)              // n-gate weights in smem
#define GR_SMEM_BYTES (GR_WN_FLOATS * 4)     // 65792 (dynamic)

// f16 mma tiles: 128x128, k-chunk 64, 3-stage cp.async
#define LT_A_BYTES 16384
#define LT_STAGE   32768
#define LT_SMEM    (3 * LT_STAGE)            // 98304

// ---------------- device scratch ----------------
__device__ float g_xg_enc[M_ENC * G_SZ];
__device__ float g_xg_dec[M_DEC * G_SZ];
__device__ __align__(16) unsigned short g_a_h[M_ALL * H_SZ];      // gathered emb fp16
__device__ __align__(16) unsigned short g_wih_h[2 * G_SZ * H_SZ]; // fp16 Wih (enc,dec)
__device__ __align__(16) unsigned short g_dech_h[M_DEC * H_SZ];   // fp16 dec hidden
__device__ __align__(16) unsigned short g_fcw_h[V_OUT * H_SZ];    // fp16 fc_W

// ---------------- helpers ----------------
__device__ __forceinline__ unsigned long long pack64(float lo, float hi) {
    unsigned long long d;
    asm("mov.b64 %0, {%1,%2};" : "=l"(d) : "f"(lo), "f"(hi));
    return d;
}
__device__ __forceinline__ unsigned smem_u32(const void* p) {
    unsigned a;
    asm("{ .reg .u64 t; cvta.to.shared.u64 t, %1; cvt.u32.u64 %0, t; }"
        : "=r"(a) : "l"(p));
    return a;
}
__device__ __forceinline__ unsigned short f2h(float x) {
    unsigned short h;
    asm("cvt.rn.f16.f32 %0, %1;" : "=h"(h) : "f"(x));
    return h;
}
__device__ __forceinline__ unsigned pack_h2(float lo, float hi) {
    unsigned r;
    asm("cvt.rn.f16x2.f32 %0, %1, %2;" : "=r"(r) : "f"(hi), "f"(lo));
    return r;
}
__device__ __forceinline__ void mma_f16(float* d,
                                        unsigned a0, unsigned a1, unsigned a2, unsigned a3,
                                        unsigned b0, unsigned b1) {
    asm volatile(
        "mma.sync.aligned.m16n8k16.row.col.f32.f16.f16.f32 "
        "{%0,%1,%2,%3}, {%4,%5,%6,%7}, {%8,%9}, {%0,%1,%2,%3};"
        : "+f"(d[0]), "+f"(d[1]), "+f"(d[2]), "+f"(d[3])
        : "r"(a0), "r"(a1), "r"(a2), "r"(a3), "r"(b0), "r"(b1));
}

#define LDSM_X4(r0, r1, r2, r3, a) \
    asm volatile("ldmatrix.sync.aligned.m8n8.x4.shared.b16 {%0,%1,%2,%3}, [%4];" \
                 : "=r"(r0), "=r"(r1), "=r"(r2), "=r"(r3) : "r"(a))

#define CP_ASYNC16(dst, src) \
    asm volatile("cp.async.cg.shared.global [%0], [%1], 16;" \
                 :: "r"(dst), "l"(src) : "memory")

#define MBAR_INIT(addr, cnt) \
    asm volatile("mbarrier.init.shared.b64 [%0], %1;" :: "r"(addr), "r"(cnt) : "memory")

#define MBAR_EXPECT(addr, bytes) \
    asm volatile("mbarrier.arrive.expect_tx.shared.b64 _, [%0], %1;" \
                 :: "r"(addr), "r"(bytes) : "memory")

#define MBAR_WAIT(addr, parity) do {                                          \
    unsigned _mb = (addr), _ph = (unsigned)(parity);                          \
    asm volatile("{\n\t.reg .pred P;\n\t"                                     \
        "WL_%=:\n\t"                                                          \
        "mbarrier.try_wait.parity.acquire.cta.shared::cta.b64 P, [%0], %1, 0x989680;\n\t" \
        "@P bra.uni WD_%=;\n\t"                                               \
        "bra.uni WL_%=;\n\t"                                                  \
        "WD_%=:\n\t}" :: "r"(_mb), "r"(_ph) : "memory");                      \
} while (0)

// ---------------- kernel 0a: fc_W fp32 -> fp16 ----------------
__global__ void __launch_bounds__(256) cvt_w(const float* __restrict__ fcW) {
    long i = ((long)blockIdx.x * 256 + threadIdx.x) * 8;
    float4 v0 = *(const float4*)(fcW + i);
    float4 v1 = *(const float4*)(fcW + i + 4);
    uint4 o;
    o.x = pack_h2(v0.x, v0.y); o.y = pack_h2(v0.z, v0.w);
    o.z = pack_h2(v1.x, v1.y); o.w = pack_h2(v1.z, v1.w);
    *(uint4*)(g_fcw_h + i) = o;
}

// ---------------- kernel 0b: Wih (enc+dec) fp32 -> fp16 ----------------
__global__ void __launch_bounds__(256) cvt_wih(const float* __restrict__ encW,
                                               const float* __restrict__ decW) {
    long idx = (long)blockIdx.x * 256 + threadIdx.x;
    long i = idx * 8;
    const long half = (long)G_SZ * H_SZ;
    const float* s = (i < half) ? (encW + i) : (decW + i - half);
    float4 v0 = *(const float4*)s;
    float4 v1 = *(const float4*)(s + 4);
    uint4 o;
    o.x = pack_h2(v0.x, v0.y); o.y = pack_h2(v0.z, v0.w);
    o.z = pack_h2(v1.x, v1.y); o.w = pack_h2(v1.z, v1.w);
    *(uint4*)(g_wih_h + i) = o;
}

// ---------------- kernel 0c: gather emb rows -> dense fp16 A --------------
__global__ void __launch_bounds__(256) gather_a(
    const float* __restrict__ enc_emb, const float* __restrict__ dec_emb,
    const int* __restrict__ src, const int* __restrict__ trg)
{
    int idx = blockIdx.x * 256 + threadIdx.x;
    int gm = idx >> 5;
    int q  = idx & 31;
    const float* emb;
    int tok;
    if (gm < M_ENC) {
        tok = src[gm];
        emb = enc_emb;
    } else {
        int g2 = gm - M_ENC;
        int t = g2 & 31, b = g2 >> 5;
        tok = (t == 0) ? 1 : trg[b * T_DEC + t - 1];
        emb = dec_emb;
    }
    const float* s = emb + (long)tok * H_SZ + q * 8;
    float4 v0 = *(const float4*)s;
    float4 v1 = *(const float4*)(s + 4);
    uint4 o;
    o.x = pack_h2(v0.x, v0.y); o.y = pack_h2(v0.z, v0.w);
    o.z = pack_h2(v1.x, v1.y); o.w = pack_h2(v1.z, v1.w);
    *(uint4*)(g_a_h + (long)gm * H_SZ + q * 8) = o;
}

// ---------------- kernel 1: xg via fp16 mma (128x128 tile) -----------------
__global__ void __launch_bounds__(128, 2) xg_f16(
    const float* __restrict__ enc_bih, const float* __restrict__ dec_bih)
{
    extern __shared__ __align__(16) char smc[];
    const unsigned sb = smem_u32(smc);
    const int tid = threadIdx.x;
    const int warp = tid >> 5, lane = tid & 31;
    const int group = lane >> 2, tig = lane & 3;
    const int m_blk = blockIdx.x * 128;
    const int n_blk = blockIdx.y * 128;
    const int m_w = (warp >> 1) * 64;
    const int n_w = (warp & 1) * 64;
    const bool enc = (m_blk < M_ENC);
    const unsigned short* wih = g_wih_h + (enc ? 0 : (long)G_SZ * H_SZ);
    const float* bias = enc ? enc_bih : dec_bih;

    const unsigned short* arow[8];
    const unsigned short* brow[8];
    int us[8];
#pragma unroll
    for (int i = 0; i < 8; i++) {
        int f = i * 128 + tid;
        int r = f >> 3;
        us[i] = f & 7;
        arow[i] = g_a_h + (long)(m_blk + r) * H_SZ;
        brow[i] = wih + (long)(n_blk + r) * H_SZ;
    }

#define XG_ISSUE(c_, s_) do {                                                 \
    unsigned ab_ = sb + (s_) * LT_STAGE;                                      \
    unsigned bb_ = ab_ + LT_A_BYTES;                                          \
    _Pragma("unroll")                                                         \
    for (int i_ = 0; i_ < 8; i_++) {                                          \
        int f_ = i_ * 128 + tid;                                              \
        int r_ = f_ >> 3, u_ = us[i_];                                        \
        unsigned d_ = ab_ + r_ * 128 + ((u_ ^ (r_ & 7)) << 4);                \
        CP_ASYNC16(d_, arow[i_] + (c_) * 64 + u_ * 8);                        \
    }                                                                         \
    _Pragma("unroll")                                                         \
    for (int i_ = 0; i_ < 8; i_++) {                                          \
        int f_ = i_ * 128 + tid;                                              \
        int r_ = f_ >> 3, u_ = us[i_];                                        \
        unsigned d_ = bb_ + r_ * 128 + ((u_ ^ (r_ & 7)) << 4);                \
        CP_ASYNC16(d_, brow[i_] + (c_) * 64 + u_ * 8);                        \
    }                                                                         \
    asm volatile("cp.async.commit_group;" ::: "memory");                      \
} while (0)

    float acc[4][8][4];
#pragma unroll
    for (int i = 0; i < 4; i++)
#pragma unroll
        for (int jn = 0; jn < 8; jn++)
#pragma unroll
            for (int k = 0; k < 4; k++) acc[i][jn][k] = 0.f;

    XG_ISSUE(0, 0);
    XG_ISSUE(1, 1);
    XG_ISSUE(2, 2);

    const int a_row0 = m_w + ((lane >> 3) & 1) * 8 + (lane & 7);
    const int a_usel = lane >> 4;
    const int b_row0 = n_w + (lane & 7);
    const int b_usel = lane >> 3;

#pragma unroll
    for (int c = 0; c < 4; c++) {
        if (c == 0 || c == 1) asm volatile("cp.async.wait_group 2;" ::: "memory");
        else if (c == 2)      asm volatile("cp.async.wait_group 1;" ::: "memory");
        else                  asm volatile("cp.async.wait_group 0;" ::: "memory");
        __syncthreads();

        unsigned ab = sb + (c % 3) * LT_STAGE;
        unsigned bb = ab + LT_A_BYTES;

        unsigned bf[8][4];
#pragma unroll
        for (int ks = 0; ks < 4; ks++) {
            if ((ks & 1) == 0) {
                const int p = ks >> 1;
#pragma unroll
                for (int ni = 0; ni < 8; ni++) {
                    int row = b_row0 + ni * 8;
                    int u = 4 * p + b_usel;
                    unsigned addr = bb + row * 128 + ((u ^ (row & 7)) << 4);
                    LDSM_X4(bf[ni][0], bf[ni][1], bf[ni][2], bf[ni][3], addr);
                }
            }
            unsigned af[4][4];
#pragma unroll
            for (int mi = 0; mi < 4; mi++) {
                int row = a_row0 + mi * 16;
                int u = 2 * ks + a_usel;
                unsigned addr = ab + row * 128 + ((u ^ (row & 7)) << 4);
                LDSM_X4(af[mi][0], af[mi][1], af[mi][2], af[mi][3], addr);
            }
            const int h = (ks & 1) * 2;
#pragma unroll
            for (int mi = 0; mi < 4; mi++)
#pragma unroll
                for (int ni = 0; ni < 8; ni++)
                    mma_f16(acc[mi][ni], af[mi][0], af[mi][1], af[mi][2], af[mi][3],
                            bf[ni][h], bf[ni][h + 1]);
        }
        __syncthreads();
        if (c == 0) XG_ISSUE(3, 0);
    }

    float* xout = enc ? (g_xg_enc + (long)m_blk * G_SZ)
                      : (g_xg_dec + (long)(m_blk - M_ENC) * G_SZ);
#pragma unroll
    for (int mi = 0; mi < 4; mi++) {
        int rm0 = m_w + mi * 16 + group;
#pragma unroll
        for (int ni = 0; ni < 8; ni++) {
            int gn = n_blk + n_w + ni * 8 + tig * 2;
            float2 bbv = *(const float2*)(bias + gn);
            float2 o0, o1;
            o0.x = acc[mi][ni][0] + bbv.x; o0.y = acc[mi][ni][1] + bbv.y;
            o1.x = acc[mi][ni][2] + bbv.x; o1.y = acc[mi][ni][3] + bbv.y;
            *(float2*)(xout + (long)rm0 * G_SZ + gn)       = o0;
            *(float2*)(xout + (long)(rm0 + 8) * G_SZ + gn) = o1;
        }
    }
#undef XG_ISSUE
}

// ---------------- kernel 2: cluster GRU v5 (R10 revert) --------------------
// 32 clusters x 4 CTAs; cluster owns 2 batches; CTA rank owns 64 channels.
// r,z gate weights REGISTER-resident (64 floats each per thread, reloaded per
// phase); n gate weights in smem [64][257] (conflict-free). Scalar-FFMA dot
// with per-batch accumulators. h layout [buf][k][b] float2 (broadcast LDS.64).
// Exchange: 64 reducers x st.async.b64 x 4 ranks, mbarrier complete_tx.
__global__ void __launch_bounds__(256)
__cluster_dims__(GR_RANKS, 1, 1)
gru_rec(const float* __restrict__ encWhh, const float* __restrict__ encBhh,
        const float* __restrict__ decWhh, const float* __restrict__ decBhh)
{
    extern __shared__ __align__(16) float wn_s[];    // [64][257]
    __shared__ __align__(16) float h_s[2 * 512];     // [buf][k][b]
    __shared__ __align__(16) float redm[64 * 25];    // [ch][g*8 + b*4 + ksl]
    __shared__ __align__(16) unsigned long long h_mb[2];

    const int tid  = threadIdx.x;
    const int j    = tid & 63;   // channel within CTA
    const int ksl  = tid >> 6;   // k-slice (64 k each)
    const int rank = blockIdx.x & (GR_RANKS - 1);
    const int cid  = blockIdx.x >> 2;

    for (int i = tid; i < 1024; i += 256) h_s[i] = 0.f;
    if (tid == 0) {
        MBAR_INIT(smem_u32(&h_mb[0]), 1);
        MBAR_INIT(smem_u32(&h_mb[1]), 1);
        MBAR_EXPECT(smem_u32(&h_mb[0]), 2048u);
        MBAR_EXPECT(smem_u32(&h_mb[1]), 2048u);
    }
    __syncthreads();
    asm volatile("barrier.cluster.arrive.aligned;" ::: "memory");
    asm volatile("barrier.cluster.wait.aligned;" ::: "memory");

    const bool is_red = (tid < 64);
    const int cg  = rank * 64 + j;
    const unsigned h_base = smem_u32(h_s);
    const unsigned mb_base = smem_u32(&h_mb[0]);

    int buf = 0;
    int par0 = 0, par1 = 0;
    bool first = true;
    for (int ph = 0; ph < 2; ph++) {
        const int T = ph ? T_DEC : T_ENC;
        const float* xg  = ph ? g_xg_dec : g_xg_enc;
        const float* Bhh = ph ? decBhh : encBhh;
        const float* Wp  = ph ? decWhh : encWhh;

        // r,z weights into registers: this thread's (ch=j, k-slice=ksl*64..+64)
        float wr[64], wz[64];
        {
            const float* pr = Wp + (long)(0 * H_SZ + rank * 64 + j) * H_SZ + ksl * 64;
            const float* pz = Wp + (long)(1 * H_SZ + rank * 64 + j) * H_SZ + ksl * 64;
#pragma unroll
            for (int q = 0; q < 16; q++) {
                float4 a = __ldg((const float4*)(pr + q * 4));
                wr[q*4+0]=a.x; wr[q*4+1]=a.y; wr[q*4+2]=a.z; wr[q*4+3]=a.w;
                float4 b = __ldg((const float4*)(pz + q * 4));
                wz[q*4+0]=b.x; wz[q*4+1]=b.y; wz[q*4+2]=b.z; wz[q*4+3]=b.w;
            }
        }
        // n weights into smem [ch][257]
        for (int fid = tid; fid < 64 * 64; fid += 256) {
            int q = fid & 63;
            int ch = fid >> 6;
            float4 v = __ldg((const float4*)(Wp + (long)(2 * H_SZ + rank * 64 + ch) * H_SZ + q * 4));
            float* dst = wn_s + ch * 257 + q * 4;
            dst[0] = v.x; dst[1] = v.y; dst[2] = v.z; dst[3] = v.w;
        }
        float br = 0.f, bz = 0.f, bn = 0.f;
        if (is_red) {
            br = __ldg(Bhh + cg);
            bz = __ldg(Bhh + H_SZ + cg);
            bn = __ldg(Bhh + 2 * H_SZ + cg);
        }
        __syncthreads();

        const float* wn = wn_s + j * 257 + ksl * 64;

        for (int t = 0; t < T; t++) {
            if (!first) {
                unsigned mb = mb_base + buf * 8;
                int par = buf ? par1 : par0;
                MBAR_WAIT(mb, par);
                if (buf) par1 ^= 1; else par0 ^= 1;
                if (tid == 0) MBAR_EXPECT(mb, 2048u);
            }
            first = false;

            float xr[2], xz[2], xn[2];
            if (is_red) {
#pragma unroll
                for (int b = 0; b < 2; b++) {
                    const int bg = cid * GR_BPC + b;
                    const float* xp = xg + (long)(bg * T + t) * G_SZ + cg;
                    xr[b] = __ldg(xp); xz[b] = __ldg(xp + H_SZ); xn[b] = __ldg(xp + 2 * H_SZ);
                }
            }

            // scalar-FFMA dot over this thread's 64-k slice, both batches
            float ar0 = 0.f, ar1 = 0.f, az0 = 0.f, az1 = 0.f, an0 = 0.f, an1 = 0.f;
            const float* hb = h_s + buf * 512 + ksl * 128;
#pragma unroll
            for (int kk = 0; kk < 64; kk++) {
                float2 hv = *(const float2*)(hb + kk * 2);
                float wnv = wn[kk];
                ar0 += hv.x * wr[kk]; ar1 += hv.y * wr[kk];
                az0 += hv.x * wz[kk]; az1 += hv.y * wz[kk];
                an0 += hv.x * wnv;    an1 += hv.y * wnv;
            }
            {
                float* rp = redm + j * 25;
                rp[0 * 8 + 0 + ksl] = ar0; rp[0 * 8 + 4 + ksl] = ar1;
                rp[1 * 8 + 0 + ksl] = az0; rp[1 * 8 + 4 + ksl] = az1;
                rp[2 * 8 + 0 + ksl] = an0; rp[2 * 8 + 4 + ksl] = an1;
            }
            __syncthreads();

            if (is_red) {
                float hnew[2];
#pragma unroll
                for (int b = 0; b < 2; b++) {
                    float s[3];
#pragma unroll
                    for (int g = 0; g < 3; g++) {
                        const float* rp = redm + j * 25 + g * 8 + b * 4;
                        s[g] = (rp[0] + rp[1]) + (rp[2] + rp[3]);
                    }
                    float hold = h_s[buf * 512 + cg * 2 + b];
                    float r = 1.f / (1.f + __expf(-(xr[b] + s[0] + br)));
                    float z = 1.f / (1.f + __expf(-(xz[b] + s[1] + bz)));
                    float n = tanhf(xn[b] + r * (s[2] + bn));
                    hnew[b] = (1.f - z) * n + z * hold;
                }

                const int nb = buf ^ 1;
                unsigned long long hp = pack64(hnew[0], hnew[1]);
                unsigned laddr = h_base + (unsigned)((nb * 512 + cg * 2) * 4);
                unsigned lmb   = mb_base + nb * 8;
#pragma unroll
                for (int rr = 0; rr < GR_RANKS; rr++) {
                    unsigned ra, rm;
                    asm volatile("mapa.shared::cluster.u32 %0, %1, %2;"
                                 : "=r"(ra) : "r"(laddr), "r"(rr));
                    asm volatile("mapa.shared::cluster.u32 %0, %1, %2;"
                                 : "=r"(rm) : "r"(lmb), "r"(rr));
                    asm volatile(
                        "st.async.shared::cluster.mbarrier::complete_tx::bytes.b64 [%0], %1, [%2];"
                        :: "r"(ra), "l"(hp), "r"(rm) : "memory");
                }
                if (ph) {
#pragma unroll
                    for (int b = 0; b < 2; b++) {
                        const int bg = cid * GR_BPC + b;
                        g_dech_h[(long)(bg * T_DEC + t) * H_SZ + cg] = f2h(hnew[b]);
                    }
                }
            }
            buf ^= 1;
        }
        __syncthreads();   // all threads past redm reads before next phase reloads
    }
    {
        unsigned mb = mb_base + buf * 8;
        int par = buf ? par1 : par0;
        MBAR_WAIT(mb, par);
    }
    asm volatile("barrier.cluster.arrive.aligned;" ::: "memory");
    asm volatile("barrier.cluster.wait.aligned;" ::: "memory");
}

// ---------------- kernel 3: logits, 4 warps x 64x64, 3-stage cp.async ------
__global__ void __launch_bounds__(128, 2) logits_f16(
    const float* __restrict__ fcb, float* __restrict__ out)
{
    extern __shared__ __align__(16) char smc[];
    const unsigned sb = smem_u32(smc);
    const int tid = threadIdx.x;
    const int warp = tid >> 5, lane = tid & 31;
    const int group = lane >> 2, tig = lane & 3;
    const int m_blk = blockIdx.x * 128;
    const int n_blk = blockIdx.y * 128;
    const int m_w = (warp >> 1) * 64;
    const int n_w = (warp & 1) * 64;

#define LT_ISSUE(c_, s_) do {                                                 \
    unsigned ab_ = sb + (s_) * LT_STAGE;                                      \
    unsigned bb_ = ab_ + LT_A_BYTES;                                          \
    _Pragma("unroll")                                                         \
    for (int i_ = 0; i_ < 8; i_++) {                                          \
        int f_ = i_ * 128 + tid;                                              \
        int r_ = f_ >> 3, u_ = f_ & 7;                                        \
        unsigned d_ = ab_ + r_ * 128 + ((u_ ^ (r_ & 7)) << 4);                \
        const void* s2_ = g_dech_h + (long)(m_blk + r_) * 256 + (c_) * 64 + u_ * 8; \
        CP_ASYNC16(d_, s2_);                                                  \
    }                                                                         \
    _Pragma("unroll")                                                         \
    for (int i_ = 0; i_ < 8; i_++) {                                          \
        int f_ = i_ * 128 + tid;                                              \
        int r_ = f_ >> 3, u_ = f_ & 7;                                        \
        unsigned d_ = bb_ + r_ * 128 + ((u_ ^ (r_ & 7)) << 4);                \
        const void* s2_ = g_fcw_h + (long)(n_blk + r_) * 256 + (c_) * 64 + u_ * 8; \
        CP_ASYNC16(d_, s2_);                                                  \
    }                                                                         \
    asm volatile("cp.async.commit_group;" ::: "memory");                      \
} while (0)

    float acc[4][8][4];
#pragma unroll
    for (int i = 0; i < 4; i++)
#pragma unroll
        for (int jn = 0; jn < 8; jn++)
#pragma unroll
            for (int k = 0; k < 4; k++) acc[i][jn][k] = 0.f;

    LT_ISSUE(0, 0);
    LT_ISSUE(1, 1);
    LT_ISSUE(2, 2);

    const int a_row0 = m_w + ((lane >> 3) & 1) * 8 + (lane & 7);
    const int a_usel = lane >> 4;
    const int b_row0 = n_w + (lane & 7);
    const int b_usel = lane >> 3;

#pragma unroll
    for (int c = 0; c < 4; c++) {
        if (c == 0 || c == 1) asm volatile("cp.async.wait_group 2;" ::: "memory");
        else if (c == 2)      asm volatile("cp.async.wait_group 1;" ::: "memory");
        else                  asm volatile("cp.async.wait_group 0;" ::: "memory");
        __syncthreads();

        unsigned ab = sb + (c % 3) * LT_STAGE;
        unsigned bb = ab + LT_A_BYTES;

        unsigned bf[8][4];
#pragma unroll
        for (int ks = 0; ks < 4; ks++) {
            if ((ks & 1) == 0) {
                const int p = ks >> 1;
#pragma unroll
                for (int ni = 0; ni < 8; ni++) {
                    int row = b_row0 + ni * 8;
                    int u = 4 * p + b_usel;
                    unsigned addr = bb + row * 128 + ((u ^ (row & 7)) << 4);
                    LDSM_X4(bf[ni][0], bf[ni][1], bf[ni][2], bf[ni][3], addr);
                }
            }
            unsigned af[4][4];
#pragma unroll
            for (int mi = 0; mi < 4; mi++) {
                int row = a_row0 + mi * 16;
                int u = 2 * ks + a_usel;
                unsigned addr = ab + row * 128 + ((u ^ (row & 7)) << 4);
                LDSM_X4(af[mi][0], af[mi][1], af[mi][2], af[mi][3], addr);
            }
            const int h = (ks & 1) * 2;
#pragma unroll
            for (int mi = 0; mi < 4; mi++)
#pragma unroll
                for (int ni = 0; ni < 8; ni++)
                    mma_f16(acc[mi][ni], af[mi][0], af[mi][1], af[mi][2], af[mi][3],
                            bf[ni][h], bf[ni][h + 1]);
        }
        __syncthreads();
        if (c == 0) LT_ISSUE(3, 0);
    }

#pragma unroll
    for (int mi = 0; mi < 4; mi++) {
        int gm0 = m_blk + m_w + mi * 16 + group;
#pragma unroll
        for (int ni = 0; ni < 8; ni++) {
            int gn = n_blk + n_w + ni * 8 + tig * 2;
            float2 bbv = *(const float2*)(fcb + gn);
            float2 o0, o1;
            o0.x = acc[mi][ni][0] + bbv.x; o0.y = acc[mi][ni][1] + bbv.y;
            o1.x = acc[mi][ni][2] + bbv.x; o1.y = acc[mi][ni][3] + bbv.y;
            *(float2*)(out + (long)gm0 * V_OUT + gn)       = o0;
            *(float2*)(out + (long)(gm0 + 8) * V_OUT + gn) = o1;
        }
    }
#undef LT_ISSUE
}

// ---------------- launch ----------------
extern "C" void kernel_launch(void* const* d_in, const int* in_sizes, int n_in,
                              void* d_out, int out_size) {
    const int*   src     = (const int*)  d_in[0];
    const int*   trg     = (const int*)  d_in[1];
    const float* enc_emb = (const float*)d_in[2];
    const float* enc_Wih = (const float*)d_in[3];
    const float* enc_Whh = (const float*)d_in[4];
    const float* enc_bih = (const float*)d_in[5];
    const float* enc_bhh = (const float*)d_in[6];
    const float* dec_emb = (const float*)d_in[7];
    const float* dec_Wih = (const float*)d_in[8];
    const float* dec_Whh = (const float*)d_in[9];
    const float* dec_bih = (const float*)d_in[10];
    const float* dec_bhh = (const float*)d_in[11];
    const float* fc_W    = (const float*)d_in[12];
    const float* fc_b    = (const float*)d_in[13];
    float* out = (float*)d_out;

    static bool attr_done = false;
    if (!attr_done) {
        cudaFuncSetAttribute((const void*)gru_rec,
                             cudaFuncAttributeMaxDynamicSharedMemorySize,
                             GR_SMEM_BYTES);
        cudaFuncSetAttribute((const void*)logits_f16,
                             cudaFuncAttributeMaxDynamicSharedMemorySize,
                             LT_SMEM);
        cudaFuncSetAttribute((const void*)xg_f16,
                             cudaFuncAttributeMaxDynamicSharedMemorySize,
                             LT_SMEM);
        attr_done = true;
    }

    cvt_w<<<V_OUT * H_SZ / (256 * 8), 256>>>(fc_W);
    cvt_wih<<<2 * G_SZ * H_SZ / (256 * 8), 256>>>(enc_Wih, dec_Wih);
    gather_a<<<M_ALL * 32 / 256, 256>>>(enc_emb, dec_emb, src, trg);
    xg_f16<<<dim3(M_ALL / 128, G_SZ / 128), 128, LT_SMEM>>>(enc_bih, dec_bih);
    gru_rec<<<GR_CTAS, 256, GR_SMEM_BYTES>>>(enc_Whh, enc_bhh, dec_Whh, dec_bhh);
    logits_f16<<<dim3(M_DEC / 128, V_OUT / 128), 128, LT_SMEM>>>(fc_b, out);
}

// round 13
// speedup vs baseline: 1.3753x; 1.0238x over previous
#include <cuda_runtime.h>
#include <cstdint>

#define B_SZ   64
#define H_SZ   256
#define G_SZ   768            // 3*H
#define T_ENC  48
#define T_DEC  32
#define V_OUT  32000
#define M_ENC  (B_SZ * T_ENC) // 3072
#define M_DEC  (B_SZ * T_DEC) // 2048
#define M_ALL  (M_ENC + M_DEC)// 5120

// gru: 32 clusters x 4 CTAs, 64 ch per CTA, 2 batches per cluster
#define GR_RANKS 4
#define GR_BPC   2
#define GR_CTAS  128
#define GR_WN_FLOATS (64 * 257)              // n-gate weights in smem
#define GR_SMEM_BYTES (GR_WN_FLOATS * 4)     // 65792 (dynamic)

// f16 mma tiles: 128x128, k-chunk 64, 3-stage cp.async
#define LT_A_BYTES 16384
#define LT_STAGE   32768
#define LT_SMEM    (3 * LT_STAGE)            // 98304

// prep kernel block ranges
#define PREP_W_BLKS   (V_OUT * H_SZ / (256 * 8))        // 4000
#define PREP_WIH_BLKS (2 * G_SZ * H_SZ / (256 * 8))     // 192
#define PREP_GA_BLKS  (M_ALL * 32 / 256)                // 640
#define PREP_BLKS     (PREP_W_BLKS + PREP_WIH_BLKS + PREP_GA_BLKS)

// ---------------- device scratch ----------------
__device__ float g_xg_enc[M_ENC * G_SZ];
__device__ float g_xg_dec[M_DEC * G_SZ];
__device__ __align__(16) unsigned short g_a_h[M_ALL * H_SZ];      // gathered emb fp16
__device__ __align__(16) unsigned short g_wih_h[2 * G_SZ * H_SZ]; // fp16 Wih (enc,dec)
__device__ __align__(16) unsigned short g_dech_h[M_DEC * H_SZ];   // fp16 dec hidden
__device__ __align__(16) unsigned short g_fcw_h[V_OUT * H_SZ];    // fp16 fc_W

// ---------------- helpers ----------------
__device__ __forceinline__ void fma2(unsigned long long& d,
                                     unsigned long long a, unsigned long long b) {
    asm("fma.rn.f32x2 %0, %1, %2, %0;" : "+l"(d) : "l"(a), "l"(b));
}
__device__ __forceinline__ void unpack2(unsigned long long v, float& lo, float& hi) {
    asm("mov.b64 {%0,%1}, %2;" : "=f"(lo), "=f"(hi) : "l"(v));
}
__device__ __forceinline__ unsigned long long dup2(float w) {
    unsigned long long d;
    asm("mov.b64 %0, {%1,%1};" : "=l"(d) : "f"(w));
    return d;
}
__device__ __forceinline__ unsigned long long pack64(float lo, float hi) {
    unsigned long long d;
    asm("mov.b64 %0, {%1,%2};" : "=l"(d) : "f"(lo), "f"(hi));
    return d;
}
__device__ __forceinline__ unsigned smem_u32(const void* p) {
    unsigned a;
    asm("{ .reg .u64 t; cvta.to.shared.u64 t, %1; cvt.u32.u64 %0, t; }"
        : "=r"(a) : "l"(p));
    return a;
}
__device__ __forceinline__ unsigned short f2h(float x) {
    unsigned short h;
    asm("cvt.rn.f16.f32 %0, %1;" : "=h"(h) : "f"(x));
    return h;
}
__device__ __forceinline__ unsigned pack_h2(float lo, float hi) {
    unsigned r;
    asm("cvt.rn.f16x2.f32 %0, %1, %2;" : "=r"(r) : "f"(hi), "f"(lo));
    return r;
}
__device__ __forceinline__ void mma_f16(float* d,
                                        unsigned a0, unsigned a1, unsigned a2, unsigned a3,
                                        unsigned b0, unsigned b1) {
    asm volatile(
        "mma.sync.aligned.m16n8k16.row.col.f32.f16.f16.f32 "
        "{%0,%1,%2,%3}, {%4,%5,%6,%7}, {%8,%9}, {%0,%1,%2,%3};"
        : "+f"(d[0]), "+f"(d[1]), "+f"(d[2]), "+f"(d[3])
        : "r"(a0), "r"(a1), "r"(a2), "r"(a3), "r"(b0), "r"(b1));
}

#define LDSM_X4(r0, r1, r2, r3, a) \
    asm volatile("ldmatrix.sync.aligned.m8n8.x4.shared.b16 {%0,%1,%2,%3}, [%4];" \
                 : "=r"(r0), "=r"(r1), "=r"(r2), "=r"(r3) : "r"(a))

#define CP_ASYNC16(dst, src) \
    asm volatile("cp.async.cg.shared.global [%0], [%1], 16;" \
                 :: "r"(dst), "l"(src) : "memory")

#define MBAR_INIT(addr, cnt) \
    asm volatile("mbarrier.init.shared.b64 [%0], %1;" :: "r"(addr), "r"(cnt) : "memory")

#define MBAR_EXPECT(addr, bytes) \
    asm volatile("mbarrier.arrive.expect_tx.shared.b64 _, [%0], %1;" \
                 :: "r"(addr), "r"(bytes) : "memory")

#define MBAR_WAIT(addr, parity) do {                                          \
    unsigned _mb = (addr), _ph = (unsigned)(parity);                          \
    asm volatile("{\n\t.reg .pred P;\n\t"                                     \
        "WL_%=:\n\t"                                                          \
        "mbarrier.try_wait.parity.acquire.cta.shared::cta.b64 P, [%0], %1, 0x989680;\n\t" \
        "@P bra.uni WD_%=;\n\t"                                               \
        "bra.uni WL_%=;\n\t"                                                  \
        "WD_%=:\n\t}" :: "r"(_mb), "r"(_ph) : "memory");                      \
} while (0)

// ---------------- kernel 0: fused prep (cvt_w | cvt_wih | gather) ----------
__global__ void __launch_bounds__(256) prep(
    const float* __restrict__ fcW,
    const float* __restrict__ encWih, const float* __restrict__ decWih,
    const float* __restrict__ enc_emb, const float* __restrict__ dec_emb,
    const int* __restrict__ src, const int* __restrict__ trg)
{
    const int b = blockIdx.x;
    if (b < PREP_W_BLKS) {
        long i = ((long)b * 256 + threadIdx.x) * 8;
        float4 v0 = *(const float4*)(fcW + i);
        float4 v1 = *(const float4*)(fcW + i + 4);
        uint4 o;
        o.x = pack_h2(v0.x, v0.y); o.y = pack_h2(v0.z, v0.w);
        o.z = pack_h2(v1.x, v1.y); o.w = pack_h2(v1.z, v1.w);
        *(uint4*)(g_fcw_h + i) = o;
    } else if (b < PREP_W_BLKS + PREP_WIH_BLKS) {
        long idx = (long)(b - PREP_W_BLKS) * 256 + threadIdx.x;
        long i = idx * 8;
        const long half = (long)G_SZ * H_SZ;
        const float* s = (i < half) ? (encWih + i) : (decWih + i - half);
        float4 v0 = *(const float4*)s;
        float4 v1 = *(const float4*)(s + 4);
        uint4 o;
        o.x = pack_h2(v0.x, v0.y); o.y = pack_h2(v0.z, v0.w);
        o.z = pack_h2(v1.x, v1.y); o.w = pack_h2(v1.z, v1.w);
        *(uint4*)(g_wih_h + i) = o;
    } else {
        int idx = (b - PREP_W_BLKS - PREP_WIH_BLKS) * 256 + threadIdx.x;
        int gm = idx >> 5;
        int q  = idx & 31;
        const float* emb;
        int tok;
        if (gm < M_ENC) {
            tok = src[gm];
            emb = enc_emb;
        } else {
            int g2 = gm - M_ENC;
            int t = g2 & 31, bb = g2 >> 5;
            tok = (t == 0) ? 1 : trg[bb * T_DEC + t - 1];
            emb = dec_emb;
        }
        const float* s = emb + (long)tok * H_SZ + q * 8;
        float4 v0 = *(const float4*)s;
        float4 v1 = *(const float4*)(s + 4);
        uint4 o;
        o.x = pack_h2(v0.x, v0.y); o.y = pack_h2(v0.z, v0.w);
        o.z = pack_h2(v1.x, v1.y); o.w = pack_h2(v1.z, v1.w);
        *(uint4*)(g_a_h + (long)gm * H_SZ + q * 8) = o;
    }
}

// ---------------- kernel 1: xg via fp16 mma (128x128 tile) -----------------
__global__ void __launch_bounds__(128, 2) xg_f16(
    const float* __restrict__ enc_bih, const float* __restrict__ dec_bih)
{
    extern __shared__ __align__(16) char smc[];
    const unsigned sb = smem_u32(smc);
    const int tid = threadIdx.x;
    const int warp = tid >> 5, lane = tid & 31;
    const int group = lane >> 2, tig = lane & 3;
    const int m_blk = blockIdx.x * 128;
    const int n_blk = blockIdx.y * 128;
    const int m_w = (warp >> 1) * 64;
    const int n_w = (warp & 1) * 64;
    const bool enc = (m_blk < M_ENC);
    const unsigned short* wih = g_wih_h + (enc ? 0 : (long)G_SZ * H_SZ);
    const float* bias = enc ? enc_bih : dec_bih;

    const unsigned short* arow[8];
    const unsigned short* brow[8];
    int us[8];
#pragma unroll
    for (int i = 0; i < 8; i++) {
        int f = i * 128 + tid;
        int r = f >> 3;
        us[i] = f & 7;
        arow[i] = g_a_h + (long)(m_blk + r) * H_SZ;
        brow[i] = wih + (long)(n_blk + r) * H_SZ;
    }

#define XG_ISSUE(c_, s_) do {                                                 \
    unsigned ab_ = sb + (s_) * LT_STAGE;                                      \
    unsigned bb_ = ab_ + LT_A_BYTES;                                          \
    _Pragma("unroll")                                                         \
    for (int i_ = 0; i_ < 8; i_++) {                                          \
        int f_ = i_ * 128 + tid;                                              \
        int r_ = f_ >> 3, u_ = us[i_];                                        \
        unsigned d_ = ab_ + r_ * 128 + ((u_ ^ (r_ & 7)) << 4);                \
        CP_ASYNC16(d_, arow[i_] + (c_) * 64 + u_ * 8);                        \
    }                                                                         \
    _Pragma("unroll")                                                         \
    for (int i_ = 0; i_ < 8; i_++) {                                          \
        int f_ = i_ * 128 + tid;                                              \
        int r_ = f_ >> 3, u_ = us[i_];                                        \
        unsigned d_ = bb_ + r_ * 128 + ((u_ ^ (r_ & 7)) << 4);                \
        CP_ASYNC16(d_, brow[i_] + (c_) * 64 + u_ * 8);                        \
    }                                                                         \
    asm volatile("cp.async.commit_group;" ::: "memory");                      \
} while (0)

    float acc[4][8][4];
#pragma unroll
    for (int i = 0; i < 4; i++)
#pragma unroll
        for (int jn = 0; jn < 8; jn++)
#pragma unroll
            for (int k = 0; k < 4; k++) acc[i][jn][k] = 0.f;

    XG_ISSUE(0, 0);
    XG_ISSUE(1, 1);
    XG_ISSUE(2, 2);

    const int a_row0 = m_w + ((lane >> 3) & 1) * 8 + (lane & 7);
    const int a_usel = lane >> 4;
    const int b_row0 = n_w + (lane & 7);
    const int b_usel = lane >> 3;

#pragma unroll
    for (int c = 0; c < 4; c++) {
        if (c == 0 || c == 1) asm volatile("cp.async.wait_group 2;" ::: "memory");
        else if (c == 2)      asm volatile("cp.async.wait_group 1;" ::: "memory");
        else                  asm volatile("cp.async.wait_group 0;" ::: "memory");
        __syncthreads();

        unsigned ab = sb + (c % 3) * LT_STAGE;
        unsigned bb = ab + LT_A_BYTES;

        unsigned bf[8][4];
#pragma unroll
        for (int ks = 0; ks < 4; ks++) {
            if ((ks & 1) == 0) {
                const int p = ks >> 1;
#pragma unroll
                for (int ni = 0; ni < 8; ni++) {
                    int row = b_row0 + ni * 8;
                    int u = 4 * p + b_usel;
                    unsigned addr = bb + row * 128 + ((u ^ (row & 7)) << 4);
                    LDSM_X4(bf[ni][0], bf[ni][1], bf[ni][2], bf[ni][3], addr);
                }
            }
            unsigned af[4][4];
#pragma unroll
            for (int mi = 0; mi < 4; mi++) {
                int row = a_row0 + mi * 16;
                int u = 2 * ks + a_usel;
                unsigned addr = ab + row * 128 + ((u ^ (row & 7)) << 4);
                LDSM_X4(af[mi][0], af[mi][1], af[mi][2], af[mi][3], addr);
            }
            const int h = (ks & 1) * 2;
#pragma unroll
            for (int mi = 0; mi < 4; mi++)
#pragma unroll
                for (int ni = 0; ni < 8; ni++)
                    mma_f16(acc[mi][ni], af[mi][0], af[mi][1], af[mi][2], af[mi][3],
                            bf[ni][h], bf[ni][h + 1]);
        }
        __syncthreads();
        if (c == 0) XG_ISSUE(3, 0);
    }

    float* xout = enc ? (g_xg_enc + (long)m_blk * G_SZ)
                      : (g_xg_dec + (long)(m_blk - M_ENC) * G_SZ);
#pragma unroll
    for (int mi = 0; mi < 4; mi++) {
        int rm0 = m_w + mi * 16 + group;
#pragma unroll
        for (int ni = 0; ni < 8; ni++) {
            int gn = n_blk + n_w + ni * 8 + tig * 2;
            float2 bbv = *(const float2*)(bias + gn);
            float2 o0, o1;
            o0.x = acc[mi][ni][0] + bbv.x; o0.y = acc[mi][ni][1] + bbv.y;
            o1.x = acc[mi][ni][2] + bbv.x; o1.y = acc[mi][ni][3] + bbv.y;
            *(float2*)(xout + (long)rm0 * G_SZ + gn)       = o0;
            *(float2*)(xout + (long)(rm0 + 8) * G_SZ + gn) = o1;
        }
    }
#undef XG_ISSUE
}

// ---------------- kernel 2: cluster GRU v7 (R12 structure, fma2 dot) -------
// 32 clusters x 4 CTAs; cluster owns 2 batches; CTA rank owns 64 channels.
// r,z gate weights REGISTER-resident; n gate weights in smem [64][257].
// fma2 packed dot (both batches per FFMA2), redm smem reduction,
// st.async b64 exchange with mbarrier complete_tx.
__global__ void __launch_bounds__(256)
__cluster_dims__(GR_RANKS, 1, 1)
gru_rec(const float* __restrict__ encWhh, const float* __restrict__ encBhh,
        const float* __restrict__ decWhh, const float* __restrict__ decBhh)
{
    extern __shared__ __align__(16) float wn_s[];    // [64][257]
    __shared__ __align__(16) float h_s[2 * 512];     // [buf][k][b]
    __shared__ __align__(16) float redm[64 * 25];    // [ch][g*8 + b*4 + ksl]
    __shared__ __align__(16) unsigned long long h_mb[2];

    const int tid  = threadIdx.x;
    const int j    = tid & 63;   // channel within CTA
    const int ksl  = tid >> 6;   // k-slice (64 k each)
    const int rank = blockIdx.x & (GR_RANKS - 1);
    const int cid  = blockIdx.x >> 2;

    for (int i = tid; i < 1024; i += 256) h_s[i] = 0.f;
    if (tid == 0) {
        MBAR_INIT(smem_u32(&h_mb[0]), 1);
        MBAR_INIT(smem_u32(&h_mb[1]), 1);
        MBAR_EXPECT(smem_u32(&h_mb[0]), 2048u);
        MBAR_EXPECT(smem_u32(&h_mb[1]), 2048u);
    }
    __syncthreads();
    asm volatile("barrier.cluster.arrive.aligned;" ::: "memory");
    asm volatile("barrier.cluster.wait.aligned;" ::: "memory");

    const bool is_red = (tid < 64);
    const int cg  = rank * 64 + j;
    const unsigned h_base = smem_u32(h_s);
    const unsigned mb_base = smem_u32(&h_mb[0]);

    int buf = 0;
    int par0 = 0, par1 = 0;
    bool first = true;
    for (int ph = 0; ph < 2; ph++) {
        const int T = ph ? T_DEC : T_ENC;
        const float* xg  = ph ? g_xg_dec : g_xg_enc;
        const float* Bhh = ph ? decBhh : encBhh;
        const float* Wp  = ph ? decWhh : encWhh;

        // r,z weights into registers: this thread's (ch=j, k-slice=ksl*64..+64)
        float wr[64], wz[64];
        {
            const float* pr = Wp + (long)(0 * H_SZ + rank * 64 + j) * H_SZ + ksl * 64;
            const float* pz = Wp + (long)(1 * H_SZ + rank * 64 + j) * H_SZ + ksl * 64;
#pragma unroll
            for (int q = 0; q < 16; q++) {
                float4 a = __ldg((const float4*)(pr + q * 4));
                wr[q*4+0]=a.x; wr[q*4+1]=a.y; wr[q*4+2]=a.z; wr[q*4+3]=a.w;
                float4 b = __ldg((const float4*)(pz + q * 4));
                wz[q*4+0]=b.x; wz[q*4+1]=b.y; wz[q*4+2]=b.z; wz[q*4+3]=b.w;
            }
        }
        // n weights into smem [ch][257]
        for (int fid = tid; fid < 64 * 64; fid += 256) {
            int q = fid & 63;
            int ch = fid >> 6;
            float4 v = __ldg((const float4*)(Wp + (long)(2 * H_SZ + rank * 64 + ch) * H_SZ + q * 4));
            float* dst = wn_s + ch * 257 + q * 4;
            dst[0] = v.x; dst[1] = v.y; dst[2] = v.z; dst[3] = v.w;
        }
        float br = 0.f, bz = 0.f, bn = 0.f;
        if (is_red) {
            br = __ldg(Bhh + cg);
            bz = __ldg(Bhh + H_SZ + cg);
            bn = __ldg(Bhh + 2 * H_SZ + cg);
        }
        __syncthreads();

        const float* wn = wn_s + j * 257 + ksl * 64;

        for (int t = 0; t < T; t++) {
            if (!first) {
                unsigned mb = mb_base + buf * 8;
                int par = buf ? par1 : par0;
                MBAR_WAIT(mb, par);
                if (buf) par1 ^= 1; else par0 ^= 1;
                if (tid == 0) MBAR_EXPECT(mb, 2048u);
            }
            first = false;

            float xr[2], xz[2], xn[2];
            if (is_red) {
#pragma unroll
                for (int b = 0; b < 2; b++) {
                    const int bg = cid * GR_BPC + b;
                    const float* xp = xg + (long)(bg * T + t) * G_SZ + cg;
                    xr[b] = __ldg(xp); xz[b] = __ldg(xp + H_SZ); xn[b] = __ldg(xp + 2 * H_SZ);
                }
            }

            // fma2 packed dot over this thread's 64-k slice (both batches)
            unsigned long long a0 = 0ull, a1 = 0ull, a2 = 0ull;
            const float* hb = h_s + buf * 512 + ksl * 128;
#pragma unroll
            for (int kk = 0; kk < 64; kk++) {
                unsigned long long hv = *(const unsigned long long*)(hb + kk * 2);
                fma2(a0, hv, dup2(wr[kk]));
                fma2(a1, hv, dup2(wz[kk]));
                fma2(a2, hv, dup2(wn[kk]));
            }
            {
                float p0, p1;
                float* rp = redm + j * 25;
                unpack2(a0, p0, p1);
                rp[0 * 8 + 0 + ksl] = p0; rp[0 * 8 + 4 + ksl] = p1;
                unpack2(a1, p0, p1);
                rp[1 * 8 + 0 + ksl] = p0; rp[1 * 8 + 4 + ksl] = p1;
                unpack2(a2, p0, p1);
                rp[2 * 8 + 0 + ksl] = p0; rp[2 * 8 + 4 + ksl] = p1;
            }
            __syncthreads();

            if (is_red) {
                float hnew[2];
#pragma unroll
                for (int b = 0; b < 2; b++) {
                    float s[3];
#pragma unroll
                    for (int g = 0; g < 3; g++) {
                        const float* rp = redm + j * 25 + g * 8 + b * 4;
                        s[g] = (rp[0] + rp[1]) + (rp[2] + rp[3]);
                    }
                    float hold = h_s[buf * 512 + cg * 2 + b];
                    float r = 1.f / (1.f + __expf(-(xr[b] + s[0] + br)));
                    float z = 1.f / (1.f + __expf(-(xz[b] + s[1] + bz)));
                    float n = tanhf(xn[b] + r * (s[2] + bn));
                    hnew[b] = (1.f - z) * n + z * hold;
                }

                const int nb = buf ^ 1;
                unsigned long long hp = pack64(hnew[0], hnew[1]);
                unsigned laddr = h_base + (unsigned)((nb * 512 + cg * 2) * 4);
                unsigned lmb   = mb_base + nb * 8;
#pragma unroll
                for (int rr = 0; rr < GR_RANKS; rr++) {
                    unsigned ra, rm;
                    asm volatile("mapa.shared::cluster.u32 %0, %1, %2;"
                                 : "=r"(ra) : "r"(laddr), "r"(rr));
                    asm volatile("mapa.shared::cluster.u32 %0, %1, %2;"
                                 : "=r"(rm) : "r"(lmb), "r"(rr));
                    asm volatile(
                        "st.async.shared::cluster.mbarrier::complete_tx::bytes.b64 [%0], %1, [%2];"
                        :: "r"(ra), "l"(hp), "r"(rm) : "memory");
                }
                if (ph) {
#pragma unroll
                    for (int b = 0; b < 2; b++) {
                        const int bg = cid * GR_BPC + b;
                        g_dech_h[(long)(bg * T_DEC + t) * H_SZ + cg] = f2h(hnew[b]);
                    }
                }
            }
            buf ^= 1;
        }
        __syncthreads();   // all threads past redm reads before next phase reloads
    }
    {
        unsigned mb = mb_base + buf * 8;
        int par = buf ? par1 : par0;
        MBAR_WAIT(mb, par);
    }
    asm volatile("barrier.cluster.arrive.aligned;" ::: "memory");
    asm volatile("barrier.cluster.wait.aligned;" ::: "memory");
}

// ---------------- kernel 3: logits, 4 warps x 64x64, 3-stage cp.async ------
__global__ void __launch_bounds__(128, 2) logits_f16(
    const float* __restrict__ fcb, float* __restrict__ out)
{
    extern __shared__ __align__(16) char smc[];
    const unsigned sb = smem_u32(smc);
    const int tid = threadIdx.x;
    const int warp = tid >> 5, lane = tid & 31;
    const int group = lane >> 2, tig = lane & 3;
    const int m_blk = blockIdx.x * 128;
    const int n_blk = blockIdx.y * 128;
    const int m_w = (warp >> 1) * 64;
    const int n_w = (warp & 1) * 64;

#define LT_ISSUE(c_, s_) do {                                                 \
    unsigned ab_ = sb + (s_) * LT_STAGE;                                      \
    unsigned bb_ = ab_ + LT_A_BYTES;                                          \
    _Pragma("unroll")                                                         \
    for (int i_ = 0; i_ < 8; i_++) {                                          \
        int f_ = i_ * 128 + tid;                                              \
        int r_ = f_ >> 3, u_ = f_ & 7;                                        \
        unsigned d_ = ab_ + r_ * 128 + ((u_ ^ (r_ & 7)) << 4);                \
        const void* s2_ = g_dech_h + (long)(m_blk + r_) * 256 + (c_) * 64 + u_ * 8; \
        CP_ASYNC16(d_, s2_);                                                  \
    }                                                                         \
    _Pragma("unroll")                                                         \
    for (int i_ = 0; i_ < 8; i_++) {                                          \
        int f_ = i_ * 128 + tid;                                              \
        int r_ = f_ >> 3, u_ = f_ & 7;                                        \
        unsigned d_ = bb_ + r_ * 128 + ((u_ ^ (r_ & 7)) << 4);                \
        const void* s2_ = g_fcw_h + (long)(n_blk + r_) * 256 + (c_) * 64 + u_ * 8; \
        CP_ASYNC16(d_, s2_);                                                  \
    }                                                                         \
    asm volatile("cp.async.commit_group;" ::: "memory");                      \
} while (0)

    float acc[4][8][4];
#pragma unroll
    for (int i = 0; i < 4; i++)
#pragma unroll
        for (int jn = 0; jn < 8; jn++)
#pragma unroll
            for (int k = 0; k < 4; k++) acc[i][jn][k] = 0.f;

    LT_ISSUE(0, 0);
    LT_ISSUE(1, 1);
    LT_ISSUE(2, 2);

    const int a_row0 = m_w + ((lane >> 3) & 1) * 8 + (lane & 7);
    const int a_usel = lane >> 4;
    const int b_row0 = n_w + (lane & 7);
    const int b_usel = lane >> 3;

#pragma unroll
    for (int c = 0; c < 4; c++) {
        if (c == 0 || c == 1) asm volatile("cp.async.wait_group 2;" ::: "memory");
        else if (c == 2)      asm volatile("cp.async.wait_group 1;" ::: "memory");
        else                  asm volatile("cp.async.wait_group 0;" ::: "memory");
        __syncthreads();

        unsigned ab = sb + (c % 3) * LT_STAGE;
        unsigned bb = ab + LT_A_BYTES;

        unsigned bf[8][4];
#pragma unroll
        for (int ks = 0; ks < 4; ks++) {
            if ((ks & 1) == 0) {
                const int p = ks >> 1;
#pragma unroll
                for (int ni = 0; ni < 8; ni++) {
                    int row = b_row0 + ni * 8;
                    int u = 4 * p + b_usel;
                    unsigned addr = bb + row * 128 + ((u ^ (row & 7)) << 4);
                    LDSM_X4(bf[ni][0], bf[ni][1], bf[ni][2], bf[ni][3], addr);
                }
            }
            unsigned af[4][4];
#pragma unroll
            for (int mi = 0; mi < 4; mi++) {
                int row = a_row0 + mi * 16;
                int u = 2 * ks + a_usel;
                unsigned addr = ab + row * 128 + ((u ^ (row & 7)) << 4);
                LDSM_X4(af[mi][0], af[mi][1], af[mi][2], af[mi][3], addr);
            }
            const int h = (ks & 1) * 2;
#pragma unroll
            for (int mi = 0; mi < 4; mi++)
#pragma unroll
                for (int ni = 0; ni < 8; ni++)
                    mma_f16(acc[mi][ni], af[mi][0], af[mi][1], af[mi][2], af[mi][3],
                            bf[ni][h], bf[ni][h + 1]);
        }
        __syncthreads();
        if (c == 0) LT_ISSUE(3, 0);
    }

#pragma unroll
    for (int mi = 0; mi < 4; mi++) {
        int gm0 = m_blk + m_w + mi * 16 + group;
#pragma unroll
        for (int ni = 0; ni < 8; ni++) {
            int gn = n_blk + n_w + ni * 8 + tig * 2;
            float2 bbv = *(const float2*)(fcb + gn);
            float2 o0, o1;
            o0.x = acc[mi][ni][0] + bbv.x; o0.y = acc[mi][ni][1] + bbv.y;
            o1.x = acc[mi][ni][2] + bbv.x; o1.y = acc[mi][ni][3] + bbv.y;
            *(float2*)(out + (long)gm0 * V_OUT + gn)       = o0;
            *(float2*)(out + (long)(gm0 + 8) * V_OUT + gn) = o1;
        }
    }
#undef LT_ISSUE
}

// ---------------- launch ----------------
extern "C" void kernel_launch(void* const* d_in, const int* in_sizes, int n_in,
                              void* d_out, int out_size) {
    const int*   src     = (const int*)  d_in[0];
    const int*   trg     = (const int*)  d_in[1];
    const float* enc_emb = (const float*)d_in[2];
    const float* enc_Wih = (const float*)d_in[3];
    const float* enc_Whh = (const float*)d_in[4];
    const float* enc_bih = (const float*)d_in[5];
    const float* enc_bhh = (const float*)d_in[6];
    const float* dec_emb = (const float*)d_in[7];
    const float* dec_Wih = (const float*)d_in[8];
    const float* dec_Whh = (const float*)d_in[9];
    const float* dec_bih = (const float*)d_in[10];
    const float* dec_bhh = (const float*)d_in[11];
    const float* fc_W    = (const float*)d_in[12];
    const float* fc_b    = (const float*)d_in[13];
    float* out = (float*)d_out;

    static bool attr_done = false;
    if (!attr_done) {
        cudaFuncSetAttribute((const void*)gru_rec,
                             cudaFuncAttributeMaxDynamicSharedMemorySize,
                             GR_SMEM_BYTES);
        cudaFuncSetAttribute((const void*)logits_f16,
                             cudaFuncAttributeMaxDynamicSharedMemorySize,
                             LT_SMEM);
        cudaFuncSetAttribute((const void*)xg_f16,
                             cudaFuncAttributeMaxDynamicSharedMemorySize,
                             LT_SMEM);
        attr_done = true;
    }

    prep<<<PREP_BLKS, 256>>>(fc_W, enc_Wih, dec_Wih, enc_emb, dec_emb, src, trg);
    xg_f16<<<dim3(M_ALL / 128, G_SZ / 128), 128, LT_SMEM>>>(enc_bih, dec_bih);
    gru_rec<<<GR_CTAS, 256, GR_SMEM_BYTES>>>(enc_Whh, enc_bhh, dec_Whh, dec_bhh);
    logits_f16<<<dim3(M_DEC / 128, V_OUT / 128), 128, LT_SMEM>>>(fc_b, out);
}

// round 14
// speedup vs baseline: 1.7042x; 1.2391x over previous
#include <cuda_runtime.h>
#include <cstdint>

#define B_SZ   64
#define H_SZ   256
#define G_SZ   768            // 3*H
#define T_ENC  48
#define T_DEC  32
#define V_OUT  32000
#define M_ENC  (B_SZ * T_ENC) // 3072
#define M_DEC  (B_SZ * T_DEC) // 2048
#define M_ALL  (M_ENC + M_DEC)// 5120

// gru: 32 clusters x 4 CTAs, 64 ch per CTA, 2 batches per cluster
#define GR_RANKS 4
#define GR_BPC   2
#define GR_CTAS  128
#define GR_WN_FLOATS (64 * 257)              // n-gate weights in smem
#define GR_SMEM_BYTES (GR_WN_FLOATS * 4)     // 65792 (dynamic)

// f16 mma tiles: 128x128, k-chunk 64, 3-stage cp.async
#define LT_A_BYTES 16384
#define LT_STAGE   32768
#define LT_SMEM    (3 * LT_STAGE)            // 98304

// prep kernel block ranges
#define PREP_W_BLKS   (V_OUT * H_SZ / (256 * 8))        // 4000
#define PREP_WIH_BLKS (2 * G_SZ * H_SZ / (256 * 8))     // 192
#define PREP_GA_BLKS  (M_ALL * 32 / 256)                // 640
#define PREP_BLKS     (PREP_W_BLKS + PREP_WIH_BLKS + PREP_GA_BLKS)

// ---------------- device scratch ----------------
__device__ float g_xg_enc[M_ENC * G_SZ];
__device__ float g_xg_dec[M_DEC * G_SZ];
__device__ __align__(16) unsigned short g_a_h[M_ALL * H_SZ];      // gathered emb fp16
__device__ __align__(16) unsigned short g_wih_h[2 * G_SZ * H_SZ]; // fp16 Wih (enc,dec)
__device__ __align__(16) unsigned short g_dech_h[M_DEC * H_SZ];   // fp16 dec hidden
__device__ __align__(16) unsigned short g_fcw_h[V_OUT * H_SZ];    // fp16 fc_W

// ---------------- helpers ----------------
__device__ __forceinline__ void fma2(unsigned long long& d,
                                     unsigned long long a, unsigned long long b) {
    asm("fma.rn.f32x2 %0, %1, %2, %0;" : "+l"(d) : "l"(a), "l"(b));
}
__device__ __forceinline__ void unpack2(unsigned long long v, float& lo, float& hi) {
    asm("mov.b64 {%0,%1}, %2;" : "=f"(lo), "=f"(hi) : "l"(v));
}
__device__ __forceinline__ unsigned long long dup2(float w) {
    unsigned long long d;
    asm("mov.b64 %0, {%1,%1};" : "=l"(d) : "f"(w));
    return d;
}
__device__ __forceinline__ unsigned long long pack64(float lo, float hi) {
    unsigned long long d;
    asm("mov.b64 %0, {%1,%2};" : "=l"(d) : "f"(lo), "f"(hi));
    return d;
}
__device__ __forceinline__ unsigned smem_u32(const void* p) {
    unsigned a;
    asm("{ .reg .u64 t; cvta.to.shared.u64 t, %1; cvt.u32.u64 %0, t; }"
        : "=r"(a) : "l"(p));
    return a;
}
__device__ __forceinline__ unsigned short f2h(float x) {
    unsigned short h;
    asm("cvt.rn.f16.f32 %0, %1;" : "=h"(h) : "f"(x));
    return h;
}
__device__ __forceinline__ unsigned pack_h2(float lo, float hi) {
    unsigned r;
    asm("cvt.rn.f16x2.f32 %0, %1, %2;" : "=r"(r) : "f"(hi), "f"(lo));
    return r;
}
__device__ __forceinline__ void mma_f16(float* d,
                                        unsigned a0, unsigned a1, unsigned a2, unsigned a3,
                                        unsigned b0, unsigned b1) {
    asm volatile(
        "mma.sync.aligned.m16n8k16.row.col.f32.f16.f16.f32 "
        "{%0,%1,%2,%3}, {%4,%5,%6,%7}, {%8,%9}, {%0,%1,%2,%3};"
        : "+f"(d[0]), "+f"(d[1]), "+f"(d[2]), "+f"(d[3])
        : "r"(a0), "r"(a1), "r"(a2), "r"(a3), "r"(b0), "r"(b1));
}

#define LDSM_X4(r0, r1, r2, r3, a) \
    asm volatile("ldmatrix.sync.aligned.m8n8.x4.shared.b16 {%0,%1,%2,%3}, [%4];" \
                 : "=r"(r0), "=r"(r1), "=r"(r2), "=r"(r3) : "r"(a))

#define CP_ASYNC16(dst, src) \
    asm volatile("cp.async.cg.shared.global [%0], [%1], 16;" \
                 :: "r"(dst), "l"(src) : "memory")

#define MBAR_INIT(addr, cnt) \
    asm volatile("mbarrier.init.shared.b64 [%0], %1;" :: "r"(addr), "r"(cnt) : "memory")

#define MBAR_EXPECT(addr, bytes) \
    asm volatile("mbarrier.arrive.expect_tx.shared.b64 _, [%0], %1;" \
                 :: "r"(addr), "r"(bytes) : "memory")

#define MBAR_WAIT(addr, parity) do {                                          \
    unsigned _mb = (addr), _ph = (unsigned)(parity);                          \
    asm volatile("{\n\t.reg .pred P;\n\t"                                     \
        "WL_%=:\n\t"                                                          \
        "mbarrier.try_wait.parity.acquire.cta.shared::cta.b64 P, [%0], %1, 0x989680;\n\t" \
        "@P bra.uni WD_%=;\n\t"                                               \
        "bra.uni WL_%=;\n\t"                                                  \
        "WD_%=:\n\t}" :: "r"(_mb), "r"(_ph) : "memory");                      \
} while (0)

// ---------------- kernel 0: fused prep (cvt_w | cvt_wih | gather) ----------
__global__ void __launch_bounds__(256) prep(
    const float* __restrict__ fcW,
    const float* __restrict__ encWih, const float* __restrict__ decWih,
    const float* __restrict__ enc_emb, const float* __restrict__ dec_emb,
    const int* __restrict__ src, const int* __restrict__ trg)
{
    const int b = blockIdx.x;
    if (b < PREP_W_BLKS) {
        long i = ((long)b * 256 + threadIdx.x) * 8;
        float4 v0 = *(const float4*)(fcW + i);
        float4 v1 = *(const float4*)(fcW + i + 4);
        uint4 o;
        o.x = pack_h2(v0.x, v0.y); o.y = pack_h2(v0.z, v0.w);
        o.z = pack_h2(v1.x, v1.y); o.w = pack_h2(v1.z, v1.w);
        *(uint4*)(g_fcw_h + i) = o;
    } else if (b < PREP_W_BLKS + PREP_WIH_BLKS) {
        long idx = (long)(b - PREP_W_BLKS) * 256 + threadIdx.x;
        long i = idx * 8;
        const long half = (long)G_SZ * H_SZ;
        const float* s = (i < half) ? (encWih + i) : (decWih + i - half);
        float4 v0 = *(const float4*)s;
        float4 v1 = *(const float4*)(s + 4);
        uint4 o;
        o.x = pack_h2(v0.x, v0.y); o.y = pack_h2(v0.z, v0.w);
        o.z = pack_h2(v1.x, v1.y); o.w = pack_h2(v1.z, v1.w);
        *(uint4*)(g_wih_h + i) = o;
    } else {
        int idx = (b - PREP_W_BLKS - PREP_WIH_BLKS) * 256 + threadIdx.x;
        int gm = idx >> 5;
        int q  = idx & 31;
        const float* emb;
        int tok;
        if (gm < M_ENC) {
            tok = src[gm];
            emb = enc_emb;
        } else {
            int g2 = gm - M_ENC;
            int t = g2 & 31, bb = g2 >> 5;
            tok = (t == 0) ? 1 : trg[bb * T_DEC + t - 1];
            emb = dec_emb;
        }
        const float* s = emb + (long)tok * H_SZ + q * 8;
        float4 v0 = *(const float4*)s;
        float4 v1 = *(const float4*)(s + 4);
        uint4 o;
        o.x = pack_h2(v0.x, v0.y); o.y = pack_h2(v0.z, v0.w);
        o.z = pack_h2(v1.x, v1.y); o.w = pack_h2(v1.z, v1.w);
        *(uint4*)(g_a_h + (long)gm * H_SZ + q * 8) = o;
    }
}

// ---------------- kernel 1: xg via fp16 mma (128x128 tile) -----------------
__global__ void __launch_bounds__(128, 2) xg_f16(
    const float* __restrict__ enc_bih, const float* __restrict__ dec_bih)
{
    extern __shared__ __align__(16) char smc[];
    const unsigned sb = smem_u32(smc);
    const int tid = threadIdx.x;
    const int warp = tid >> 5, lane = tid & 31;
    const int group = lane >> 2, tig = lane & 3;
    const int m_blk = blockIdx.x * 128;
    const int n_blk = blockIdx.y * 128;
    const int m_w = (warp >> 1) * 64;
    const int n_w = (warp & 1) * 64;
    const bool enc = (m_blk < M_ENC);
    const unsigned short* wih = g_wih_h + (enc ? 0 : (long)G_SZ * H_SZ);
    const float* bias = enc ? enc_bih : dec_bih;

    const unsigned short* arow[8];
    const unsigned short* brow[8];
    int us[8];
#pragma unroll
    for (int i = 0; i < 8; i++) {
        int f = i * 128 + tid;
        int r = f >> 3;
        us[i] = f & 7;
        arow[i] = g_a_h + (long)(m_blk + r) * H_SZ;
        brow[i] = wih + (long)(n_blk + r) * H_SZ;
    }

#define XG_ISSUE(c_, s_) do {                                                 \
    unsigned ab_ = sb + (s_) * LT_STAGE;                                      \
    unsigned bb_ = ab_ + LT_A_BYTES;                                          \
    _Pragma("unroll")                                                         \
    for (int i_ = 0; i_ < 8; i_++) {                                          \
        int f_ = i_ * 128 + tid;                                              \
        int r_ = f_ >> 3, u_ = us[i_];                                        \
        unsigned d_ = ab_ + r_ * 128 + ((u_ ^ (r_ & 7)) << 4);                \
        CP_ASYNC16(d_, arow[i_] + (c_) * 64 + u_ * 8);                        \
    }                                                                         \
    _Pragma("unroll")                                                         \
    for (int i_ = 0; i_ < 8; i_++) {                                          \
        int f_ = i_ * 128 + tid;                                              \
        int r_ = f_ >> 3, u_ = us[i_];                                        \
        unsigned d_ = bb_ + r_ * 128 + ((u_ ^ (r_ & 7)) << 4);                \
        CP_ASYNC16(d_, brow[i_] + (c_) * 64 + u_ * 8);                        \
    }                                                                         \
    asm volatile("cp.async.commit_group;" ::: "memory");                      \
} while (0)

    float acc[4][8][4];
#pragma unroll
    for (int i = 0; i < 4; i++)
#pragma unroll
        for (int jn = 0; jn < 8; jn++)
#pragma unroll
            for (int k = 0; k < 4; k++) acc[i][jn][k] = 0.f;

    XG_ISSUE(0, 0);
    XG_ISSUE(1, 1);
    XG_ISSUE(2, 2);

    const int a_row0 = m_w + ((lane >> 3) & 1) * 8 + (lane & 7);
    const int a_usel = lane >> 4;
    const int b_row0 = n_w + (lane & 7);
    const int b_usel = lane >> 3;

#pragma unroll
    for (int c = 0; c < 4; c++) {
        if (c == 0 || c == 1) asm volatile("cp.async.wait_group 2;" ::: "memory");
        else if (c == 2)      asm volatile("cp.async.wait_group 1;" ::: "memory");
        else                  asm volatile("cp.async.wait_group 0;" ::: "memory");
        __syncthreads();

        unsigned ab = sb + (c % 3) * LT_STAGE;
        unsigned bb = ab + LT_A_BYTES;

        unsigned bf[8][4];
#pragma unroll
        for (int ks = 0; ks < 4; ks++) {
            if ((ks & 1) == 0) {
                const int p = ks >> 1;
#pragma unroll
                for (int ni = 0; ni < 8; ni++) {
                    int row = b_row0 + ni * 8;
                    int u = 4 * p + b_usel;
                    unsigned addr = bb + row * 128 + ((u ^ (row & 7)) << 4);
                    LDSM_X4(bf[ni][0], bf[ni][1], bf[ni][2], bf[ni][3], addr);
                }
            }
            unsigned af[4][4];
#pragma unroll
            for (int mi = 0; mi < 4; mi++) {
                int row = a_row0 + mi * 16;
                int u = 2 * ks + a_usel;
                unsigned addr = ab + row * 128 + ((u ^ (row & 7)) << 4);
                LDSM_X4(af[mi][0], af[mi][1], af[mi][2], af[mi][3], addr);
            }
            const int h = (ks & 1) * 2;
#pragma unroll
            for (int mi = 0; mi < 4; mi++)
#pragma unroll
                for (int ni = 0; ni < 8; ni++)
                    mma_f16(acc[mi][ni], af[mi][0], af[mi][1], af[mi][2], af[mi][3],
                            bf[ni][h], bf[ni][h + 1]);
        }
        __syncthreads();
        if (c == 0) XG_ISSUE(3, 0);
    }

    float* xout = enc ? (g_xg_enc + (long)m_blk * G_SZ)
                      : (g_xg_dec + (long)(m_blk - M_ENC) * G_SZ);
#pragma unroll
    for (int mi = 0; mi < 4; mi++) {
        int rm0 = m_w + mi * 16 + group;
#pragma unroll
        for (int ni = 0; ni < 8; ni++) {
            int gn = n_blk + n_w + ni * 8 + tig * 2;
            float2 bbv = *(const float2*)(bias + gn);
            float2 o0, o1;
            o0.x = acc[mi][ni][0] + bbv.x; o0.y = acc[mi][ni][1] + bbv.y;
            o1.x = acc[mi][ni][2] + bbv.x; o1.y = acc[mi][ni][3] + bbv.y;
            *(float2*)(xout + (long)rm0 * G_SZ + gn)       = o0;
            *(float2*)(xout + (long)(rm0 + 8) * G_SZ + gn) = o1;
        }
    }
#undef XG_ISSUE
}

// ---------------- kernel 2: cluster GRU v7b (R13 + minBlocks=1) ------------
// Identical to R13 except __launch_bounds__(256, 1): guarantees ptxas the full
// 255-reg budget so wr/wz stay register-resident (spill-elimination test).
__global__ void __launch_bounds__(256, 1)
__cluster_dims__(GR_RANKS, 1, 1)
gru_rec(const float* __restrict__ encWhh, const float* __restrict__ encBhh,
        const float* __restrict__ decWhh, const float* __restrict__ decBhh)
{
    extern __shared__ __align__(16) float wn_s[];    // [64][257]
    __shared__ __align__(16) float h_s[2 * 512];     // [buf][k][b]
    __shared__ __align__(16) float redm[64 * 25];    // [ch][g*8 + b*4 + ksl]
    __shared__ __align__(16) unsigned long long h_mb[2];

    const int tid  = threadIdx.x;
    const int j    = tid & 63;   // channel within CTA
    const int ksl  = tid >> 6;   // k-slice (64 k each)
    const int rank = blockIdx.x & (GR_RANKS - 1);
    const int cid  = blockIdx.x >> 2;

    for (int i = tid; i < 1024; i += 256) h_s[i] = 0.f;
    if (tid == 0) {
        MBAR_INIT(smem_u32(&h_mb[0]), 1);
        MBAR_INIT(smem_u32(&h_mb[1]), 1);
        MBAR_EXPECT(smem_u32(&h_mb[0]), 2048u);
        MBAR_EXPECT(smem_u32(&h_mb[1]), 2048u);
    }
    __syncthreads();
    asm volatile("barrier.cluster.arrive.aligned;" ::: "memory");
    asm volatile("barrier.cluster.wait.aligned;" ::: "memory");

    const bool is_red = (tid < 64);
    const int cg  = rank * 64 + j;
    const unsigned h_base = smem_u32(h_s);
    const unsigned mb_base = smem_u32(&h_mb[0]);

    int buf = 0;
    int par0 = 0, par1 = 0;
    bool first = true;
    for (int ph = 0; ph < 2; ph++) {
        const int T = ph ? T_DEC : T_ENC;
        const float* xg  = ph ? g_xg_dec : g_xg_enc;
        const float* Bhh = ph ? decBhh : encBhh;
        const float* Wp  = ph ? decWhh : encWhh;

        // r,z weights into registers: this thread's (ch=j, k-slice=ksl*64..+64)
        float wr[64], wz[64];
        {
            const float* pr = Wp + (long)(0 * H_SZ + rank * 64 + j) * H_SZ + ksl * 64;
            const float* pz = Wp + (long)(1 * H_SZ + rank * 64 + j) * H_SZ + ksl * 64;
#pragma unroll
            for (int q = 0; q < 16; q++) {
                float4 a = __ldg((const float4*)(pr + q * 4));
                wr[q*4+0]=a.x; wr[q*4+1]=a.y; wr[q*4+2]=a.z; wr[q*4+3]=a.w;
                float4 b = __ldg((const float4*)(pz + q * 4));
                wz[q*4+0]=b.x; wz[q*4+1]=b.y; wz[q*4+2]=b.z; wz[q*4+3]=b.w;
            }
        }
        // n weights into smem [ch][257]
        for (int fid = tid; fid < 64 * 64; fid += 256) {
            int q = fid & 63;
            int ch = fid >> 6;
            float4 v = __ldg((const float4*)(Wp + (long)(2 * H_SZ + rank * 64 + ch) * H_SZ + q * 4));
            float* dst = wn_s + ch * 257 + q * 4;
            dst[0] = v.x; dst[1] = v.y; dst[2] = v.z; dst[3] = v.w;
        }
        float br = 0.f, bz = 0.f, bn = 0.f;
        if (is_red) {
            br = __ldg(Bhh + cg);
            bz = __ldg(Bhh + H_SZ + cg);
            bn = __ldg(Bhh + 2 * H_SZ + cg);
        }
        __syncthreads();

        const float* wn = wn_s + j * 257 + ksl * 64;

        for (int t = 0; t < T; t++) {
            if (!first) {
                unsigned mb = mb_base + buf * 8;
                int par = buf ? par1 : par0;
                MBAR_WAIT(mb, par);
                if (buf) par1 ^= 1; else par0 ^= 1;
                if (tid == 0) MBAR_EXPECT(mb, 2048u);
            }
            first = false;

            float xr[2], xz[2], xn[2];
            if (is_red) {
#pragma unroll
                for (int b = 0; b < 2; b++) {
                    const int bg = cid * GR_BPC + b;
                    const float* xp = xg + (long)(bg * T + t) * G_SZ + cg;
                    xr[b] = __ldg(xp); xz[b] = __ldg(xp + H_SZ); xn[b] = __ldg(xp + 2 * H_SZ);
                }
            }

            // fma2 packed dot over this thread's 64-k slice (both batches)
            unsigned long long a0 = 0ull, a1 = 0ull, a2 = 0ull;
            const float* hb = h_s + buf * 512 + ksl * 128;
#pragma unroll
            for (int kk = 0; kk < 64; kk++) {
                unsigned long long hv = *(const unsigned long long*)(hb + kk * 2);
                fma2(a0, hv, dup2(wr[kk]));
                fma2(a1, hv, dup2(wz[kk]));
                fma2(a2, hv, dup2(wn[kk]));
            }
            {
                float p0, p1;
                float* rp = redm + j * 25;
                unpack2(a0, p0, p1);
                rp[0 * 8 + 0 + ksl] = p0; rp[0 * 8 + 4 + ksl] = p1;
                unpack2(a1, p0, p1);
                rp[1 * 8 + 0 + ksl] = p0; rp[1 * 8 + 4 + ksl] = p1;
                unpack2(a2, p0, p1);
                rp[2 * 8 + 0 + ksl] = p0; rp[2 * 8 + 4 + ksl] = p1;
            }
            __syncthreads();

            if (is_red) {
                float hnew[2];
#pragma unroll
                for (int b = 0; b < 2; b++) {
                    float s[3];
#pragma unroll
                    for (int g = 0; g < 3; g++) {
                        const float* rp = redm + j * 25 + g * 8 + b * 4;
                        s[g] = (rp[0] + rp[1]) + (rp[2] + rp[3]);
                    }
                    float hold = h_s[buf * 512 + cg * 2 + b];
                    float r = 1.f / (1.f + __expf(-(xr[b] + s[0] + br)));
                    float z = 1.f / (1.f + __expf(-(xz[b] + s[1] + bz)));
                    float n = tanhf(xn[b] + r * (s[2] + bn));
                    hnew[b] = (1.f - z) * n + z * hold;
                }

                const int nb = buf ^ 1;
                unsigned long long hp = pack64(hnew[0], hnew[1]);
                unsigned laddr = h_base + (unsigned)((nb * 512 + cg * 2) * 4);
                unsigned lmb   = mb_base + nb * 8;
#pragma unroll
                for (int rr = 0; rr < GR_RANKS; rr++) {
                    unsigned ra, rm;
                    asm volatile("mapa.shared::cluster.u32 %0, %1, %2;"
                                 : "=r"(ra) : "r"(laddr), "r"(rr));
                    asm volatile("mapa.shared::cluster.u32 %0, %1, %2;"
                                 : "=r"(rm) : "r"(lmb), "r"(rr));
                    asm volatile(
                        "st.async.shared::cluster.mbarrier::complete_tx::bytes.b64 [%0], %1, [%2];"
                        :: "r"(ra), "l"(hp), "r"(rm) : "memory");
                }
                if (ph) {
#pragma unroll
                    for (int b = 0; b < 2; b++) {
                        const int bg = cid * GR_BPC + b;
                        g_dech_h[(long)(bg * T_DEC + t) * H_SZ + cg] = f2h(hnew[b]);
                    }
                }
            }
            buf ^= 1;
        }
        __syncthreads();   // all threads past redm reads before next phase reloads
    }
    {
        unsigned mb = mb_base + buf * 8;
        int par = buf ? par1 : par0;
        MBAR_WAIT(mb, par);
    }
    asm volatile("barrier.cluster.arrive.aligned;" ::: "memory");
    asm volatile("barrier.cluster.wait.aligned;" ::: "memory");
}

// ---------------- kernel 3: logits, 4 warps x 64x64, 3-stage cp.async ------
__global__ void __launch_bounds__(128, 2) logits_f16(
    const float* __restrict__ fcb, float* __restrict__ out)
{
    extern __shared__ __align__(16) char smc[];
    const unsigned sb = smem_u32(smc);
    const int tid = threadIdx.x;
    const int warp = tid >> 5, lane = tid & 31;
    const int group = lane >> 2, tig = lane & 3;
    const int m_blk = blockIdx.x * 128;
    const int n_blk = blockIdx.y * 128;
    const int m_w = (warp >> 1) * 64;
    const int n_w = (warp & 1) * 64;

#define LT_ISSUE(c_, s_) do {                                                 \
    unsigned ab_ = sb + (s_) * LT_STAGE;                                      \
    unsigned bb_ = ab_ + LT_A_BYTES;                                          \
    _Pragma("unroll")                                                         \
    for (int i_ = 0; i_ < 8; i_++) {                                          \
        int f_ = i_ * 128 + tid;                                              \
        int r_ = f_ >> 3, u_ = f_ & 7;                                        \
        unsigned d_ = ab_ + r_ * 128 + ((u_ ^ (r_ & 7)) << 4);                \
        const void* s2_ = g_dech_h + (long)(m_blk + r_) * 256 + (c_) * 64 + u_ * 8; \
        CP_ASYNC16(d_, s2_);                                                  \
    }                                                                         \
    _Pragma("unroll")                                                         \
    for (int i_ = 0; i_ < 8; i_++) {                                          \
        int f_ = i_ * 128 + tid;                                              \
        int r_ = f_ >> 3, u_ = f_ & 7;                                        \
        unsigned d_ = bb_ + r_ * 128 + ((u_ ^ (r_ & 7)) << 4);                \
        const void* s2_ = g_fcw_h + (long)(n_blk + r_) * 256 + (c_) * 64 + u_ * 8; \
        CP_ASYNC16(d_, s2_);                                                  \
    }                                                                         \
    asm volatile("cp.async.commit_group;" ::: "memory");                      \
} while (0)

    float acc[4][8][4];
#pragma unroll
    for (int i = 0; i < 4; i++)
#pragma unroll
        for (int jn = 0; jn < 8; jn++)
#pragma unroll
            for (int k = 0; k < 4; k++) acc[i][jn][k] = 0.f;

    LT_ISSUE(0, 0);
    LT_ISSUE(1, 1);
    LT_ISSUE(2, 2);

    const int a_row0 = m_w + ((lane >> 3) & 1) * 8 + (lane & 7);
    const int a_usel = lane >> 4;
    const int b_row0 = n_w + (lane & 7);
    const int b_usel = lane >> 3;

#pragma unroll
    for (int c = 0; c < 4; c++) {
        if (c == 0 || c == 1) asm volatile("cp.async.wait_group 2;" ::: "memory");
        else if (c == 2)      asm volatile("cp.async.wait_group 1;" ::: "memory");
        else                  asm volatile("cp.async.wait_group 0;" ::: "memory");
        __syncthreads();

        unsigned ab = sb + (c % 3) * LT_STAGE;
        unsigned bb = ab + LT_A_BYTES;

        unsigned bf[8][4];
#pragma unroll
        for (int ks = 0; ks < 4; ks++) {
            if ((ks & 1) == 0) {
                const int p = ks >> 1;
#pragma unroll
                for (int ni = 0; ni < 8; ni++) {
                    int row = b_row0 + ni * 8;
                    int u = 4 * p + b_usel;
                    unsigned addr = bb + row * 128 + ((u ^ (row & 7)) << 4);
                    LDSM_X4(bf[ni][0], bf[ni][1], bf[ni][2], bf[ni][3], addr);
                }
            }
            unsigned af[4][4];
#pragma unroll
            for (int mi = 0; mi < 4; mi++) {
                int row = a_row0 + mi * 16;
                int u = 2 * ks + a_usel;
                unsigned addr = ab + row * 128 + ((u ^ (row & 7)) << 4);
                LDSM_X4(af[mi][0], af[mi][1], af[mi][2], af[mi][3], addr);
            }
            const int h = (ks & 1) * 2;
#pragma unroll
            for (int mi = 0; mi < 4; mi++)
#pragma unroll
                for (int ni = 0; ni < 8; ni++)
                    mma_f16(acc[mi][ni], af[mi][0], af[mi][1], af[mi][2], af[mi][3],
                            bf[ni][h], bf[ni][h + 1]);
        }
        __syncthreads();
        if (c == 0) LT_ISSUE(3, 0);
    }

#pragma unroll
    for (int mi = 0; mi < 4; mi++) {
        int gm0 = m_blk + m_w + mi * 16 + group;
#pragma unroll
        for (int ni = 0; ni < 8; ni++) {
            int gn = n_blk + n_w + ni * 8 + tig * 2;
            float2 bbv = *(const float2*)(fcb + gn);
            float2 o0, o1;
            o0.x = acc[mi][ni][0] + bbv.x; o0.y = acc[mi][ni][1] + bbv.y;
            o1.x = acc[mi][ni][2] + bbv.x; o1.y = acc[mi][ni][3] + bbv.y;
            *(float2*)(out + (long)gm0 * V_OUT + gn)       = o0;
            *(float2*)(out + (long)(gm0 + 8) * V_OUT + gn) = o1;
        }
    }
#undef LT_ISSUE
}

// ---------------- launch ----------------
extern "C" void kernel_launch(void* const* d_in, const int* in_sizes, int n_in,
                              void* d_out, int out_size) {
    const int*   src     = (const int*)  d_in[0];
    const int*   trg     = (const int*)  d_in[1];
    const float* enc_emb = (const float*)d_in[2];
    const float* enc_Wih = (const float*)d_in[3];
    const float* enc_Whh = (const float*)d_in[4];
    const float* enc_bih = (const float*)d_in[5];
    const float* enc_bhh = (const float*)d_in[6];
    const float* dec_emb = (const float*)d_in[7];
    const float* dec_Wih = (const float*)d_in[8];
    const float* dec_Whh = (const float*)d_in[9];
    const float* dec_bih = (const float*)d_in[10];
    const float* dec_bhh = (const float*)d_in[11];
    const float* fc_W    = (const float*)d_in[12];
    const float* fc_b    = (const float*)d_in[13];
    float* out = (float*)d_out;

    static bool attr_done = false;
    if (!attr_done) {
        cudaFuncSetAttribute((const void*)gru_rec,
                             cudaFuncAttributeMaxDynamicSharedMemorySize,
                             GR_SMEM_BYTES);
        cudaFuncSetAttribute((const void*)logits_f16,
                             cudaFuncAttributeMaxDynamicSharedMemorySize,
                             LT_SMEM);
        cudaFuncSetAttribute((const void*)xg_f16,
                             cudaFuncAttributeMaxDynamicSharedMemorySize,
                             LT_SMEM);
        attr_done = true;
    }

    prep<<<PREP_BLKS, 256>>>(fc_W, enc_Wih, dec_Wih, enc_emb, dec_emb, src, trg);
    xg_f16<<<dim3(M_ALL / 128, G_SZ / 128), 128, LT_SMEM>>>(enc_bih, dec_bih);
    gru_rec<<<GR_CTAS, 256, GR_SMEM_BYTES>>>(enc_Whh, enc_bhh, dec_Whh, dec_bhh);
    logits_f16<<<dim3(M_DEC / 128, V_OUT / 128), 128, LT_SMEM>>>(fc_b, out);
}

// round 15
// speedup vs baseline: 1.7141x; 1.0058x over previous
#include <cuda_runtime.h>
#include <cstdint>

#define B_SZ   64
#define H_SZ   256
#define G_SZ   768            // 3*H
#define T_ENC  48
#define T_DEC  32
#define V_OUT  32000
#define M_ENC  (B_SZ * T_ENC) // 3072
#define M_DEC  (B_SZ * T_DEC) // 2048
#define M_ALL  (M_ENC + M_DEC)// 5120

// gru: 32 clusters x 4 CTAs, 64 ch per CTA, 2 batches per cluster
#define GR_RANKS 4
#define GR_BPC   2
#define GR_CTAS  128
#define GR_WN_FLOATS (64 * 257)              // n-gate weights in smem
#define GR_SMEM_BYTES (GR_WN_FLOATS * 4)     // 65792 (dynamic)

// f16 mma tiles: 128x128, k-chunk 64, 3-stage cp.async
#define LT_A_BYTES 16384
#define LT_STAGE   32768
#define LT_SMEM    (3 * LT_STAGE)            // 98304

// prep kernel block ranges
#define PREP_W_BLKS   (V_OUT * H_SZ / (256 * 8))        // 4000
#define PREP_WIH_BLKS (2 * G_SZ * H_SZ / (256 * 8))     // 192
#define PREP_GA_BLKS  (M_ALL * 32 / 256)                // 640
#define PREP_BLKS     (PREP_W_BLKS + PREP_WIH_BLKS + PREP_GA_BLKS)

// ---------------- device scratch ----------------
__device__ float g_xg_enc[M_ENC * G_SZ];
__device__ float g_xg_dec[M_DEC * G_SZ];
__device__ __align__(16) unsigned short g_a_h[M_ALL * H_SZ];      // gathered emb fp16
__device__ __align__(16) unsigned short g_wih_h[2 * G_SZ * H_SZ]; // fp16 Wih (enc,dec)
__device__ __align__(16) unsigned short g_dech_h[M_DEC * H_SZ];   // fp16 dec hidden
__device__ __align__(16) unsigned short g_fcw_h[V_OUT * H_SZ];    // fp16 fc_W

// ---------------- helpers ----------------
__device__ __forceinline__ void fma2(unsigned long long& d,
                                     unsigned long long a, unsigned long long b) {
    asm("fma.rn.f32x2 %0, %1, %2, %0;" : "+l"(d) : "l"(a), "l"(b));
}
__device__ __forceinline__ void unpack2(unsigned long long v, float& lo, float& hi) {
    asm("mov.b64 {%0,%1}, %2;" : "=f"(lo), "=f"(hi) : "l"(v));
}
__device__ __forceinline__ unsigned long long dup2(float w) {
    unsigned long long d;
    asm("mov.b64 %0, {%1,%1};" : "=l"(d) : "f"(w));
    return d;
}
__device__ __forceinline__ unsigned long long pack64(float lo, float hi) {
    unsigned long long d;
    asm("mov.b64 %0, {%1,%2};" : "=l"(d) : "f"(lo), "f"(hi));
    return d;
}
__device__ __forceinline__ unsigned smem_u32(const void* p) {
    unsigned a;
    asm("{ .reg .u64 t; cvta.to.shared.u64 t, %1; cvt.u32.u64 %0, t; }"
        : "=r"(a) : "l"(p));
    return a;
}
__device__ __forceinline__ unsigned short f2h(float x) {
    unsigned short h;
    asm("cvt.rn.f16.f32 %0, %1;" : "=h"(h) : "f"(x));
    return h;
}
__device__ __forceinline__ unsigned pack_h2(float lo, float hi) {
    unsigned r;
    asm("cvt.rn.f16x2.f32 %0, %1, %2;" : "=r"(r) : "f"(hi), "f"(lo));
    return r;
}
__device__ __forceinline__ void mma_f16(float* d,
                                        unsigned a0, unsigned a1, unsigned a2, unsigned a3,
                                        unsigned b0, unsigned b1) {
    asm volatile(
        "mma.sync.aligned.m16n8k16.row.col.f32.f16.f16.f32 "
        "{%0,%1,%2,%3}, {%4,%5,%6,%7}, {%8,%9}, {%0,%1,%2,%3};"
        : "+f"(d[0]), "+f"(d[1]), "+f"(d[2]), "+f"(d[3])
        : "r"(a0), "r"(a1), "r"(a2), "r"(a3), "r"(b0), "r"(b1));
}

#define LDSM_X4(r0, r1, r2, r3, a) \
    asm volatile("ldmatrix.sync.aligned.m8n8.x4.shared.b16 {%0,%1,%2,%3}, [%4];" \
                 : "=r"(r0), "=r"(r1), "=r"(r2), "=r"(r3) : "r"(a))

#define CP_ASYNC16(dst, src) \
    asm volatile("cp.async.cg.shared.global [%0], [%1], 16;" \
                 :: "r"(dst), "l"(src) : "memory")

#define MBAR_INIT(addr, cnt) \
    asm volatile("mbarrier.init.shared.b64 [%0], %1;" :: "r"(addr), "r"(cnt) : "memory")

#define MBAR_EXPECT(addr, bytes) \
    asm volatile("mbarrier.arrive.expect_tx.shared.b64 _, [%0], %1;" \
                 :: "r"(addr), "r"(bytes) : "memory")

#define MBAR_WAIT(addr, parity) do {                                          \
    unsigned _mb = (addr), _ph = (unsigned)(parity);                          \
    asm volatile("{\n\t.reg .pred P;\n\t"                                     \
        "WL_%=:\n\t"                                                          \
        "mbarrier.try_wait.parity.acquire.cta.shared::cta.b64 P, [%0], %1, 0x989680;\n\t" \
        "@P bra.uni WD_%=;\n\t"                                               \
        "bra.uni WL_%=;\n\t"                                                  \
        "WD_%=:\n\t}" :: "r"(_mb), "r"(_ph) : "memory");                      \
} while (0)

// ---------------- kernel 0: fused prep (cvt_w | cvt_wih | gather) ----------
__global__ void __launch_bounds__(256) prep(
    const float* __restrict__ fcW,
    const float* __restrict__ encWih, const float* __restrict__ decWih,
    const float* __restrict__ enc_emb, const float* __restrict__ dec_emb,
    const int* __restrict__ src, const int* __restrict__ trg)
{
    const int b = blockIdx.x;
    if (b < PREP_W_BLKS) {
        long i = ((long)b * 256 + threadIdx.x) * 8;
        float4 v0 = *(const float4*)(fcW + i);
        float4 v1 = *(const float4*)(fcW + i + 4);
        uint4 o;
        o.x = pack_h2(v0.x, v0.y); o.y = pack_h2(v0.z, v0.w);
        o.z = pack_h2(v1.x, v1.y); o.w = pack_h2(v1.z, v1.w);
        *(uint4*)(g_fcw_h + i) = o;
    } else if (b < PREP_W_BLKS + PREP_WIH_BLKS) {
        long idx = (long)(b - PREP_W_BLKS) * 256 + threadIdx.x;
        long i = idx * 8;
        const long half = (long)G_SZ * H_SZ;
        const float* s = (i < half) ? (encWih + i) : (decWih + i - half);
        float4 v0 = *(const float4*)s;
        float4 v1 = *(const float4*)(s + 4);
        uint4 o;
        o.x = pack_h2(v0.x, v0.y); o.y = pack_h2(v0.z, v0.w);
        o.z = pack_h2(v1.x, v1.y); o.w = pack_h2(v1.z, v1.w);
        *(uint4*)(g_wih_h + i) = o;
    } else {
        int idx = (b - PREP_W_BLKS - PREP_WIH_BLKS) * 256 + threadIdx.x;
        int gm = idx >> 5;
        int q  = idx & 31;
        const float* emb;
        int tok;
        if (gm < M_ENC) {
            tok = src[gm];
            emb = enc_emb;
        } else {
            int g2 = gm - M_ENC;
            int t = g2 & 31, bb = g2 >> 5;
            tok = (t == 0) ? 1 : trg[bb * T_DEC + t - 1];
            emb = dec_emb;
        }
        const float* s = emb + (long)tok * H_SZ + q * 8;
        float4 v0 = *(const float4*)s;
        float4 v1 = *(const float4*)(s + 4);
        uint4 o;
        o.x = pack_h2(v0.x, v0.y); o.y = pack_h2(v0.z, v0.w);
        o.z = pack_h2(v1.x, v1.y); o.w = pack_h2(v1.z, v1.w);
        *(uint4*)(g_a_h + (long)gm * H_SZ + q * 8) = o;
    }
}

// ---------------- kernel 1: xg via fp16 mma (128x128 tile) -----------------
__global__ void __launch_bounds__(128, 2) xg_f16(
    const float* __restrict__ enc_bih, const float* __restrict__ dec_bih)
{
    extern __shared__ __align__(16) char smc[];
    const unsigned sb = smem_u32(smc);
    const int tid = threadIdx.x;
    const int warp = tid >> 5, lane = tid & 31;
    const int group = lane >> 2, tig = lane & 3;
    const int m_blk = blockIdx.x * 128;
    const int n_blk = blockIdx.y * 128;
    const int m_w = (warp >> 1) * 64;
    const int n_w = (warp & 1) * 64;
    const bool enc = (m_blk < M_ENC);
    const unsigned short* wih = g_wih_h + (enc ? 0 : (long)G_SZ * H_SZ);
    const float* bias = enc ? enc_bih : dec_bih;

    const unsigned short* arow[8];
    const unsigned short* brow[8];
    int us[8];
#pragma unroll
    for (int i = 0; i < 8; i++) {
        int f = i * 128 + tid;
        int r = f >> 3;
        us[i] = f & 7;
        arow[i] = g_a_h + (long)(m_blk + r) * H_SZ;
        brow[i] = wih + (long)(n_blk + r) * H_SZ;
    }

#define XG_ISSUE(c_, s_) do {                                                 \
    unsigned ab_ = sb + (s_) * LT_STAGE;                                      \
    unsigned bb_ = ab_ + LT_A_BYTES;                                          \
    _Pragma("unroll")                                                         \
    for (int i_ = 0; i_ < 8; i_++) {                                          \
        int f_ = i_ * 128 + tid;                                              \
        int r_ = f_ >> 3, u_ = us[i_];                                        \
        unsigned d_ = ab_ + r_ * 128 + ((u_ ^ (r_ & 7)) << 4);                \
        CP_ASYNC16(d_, arow[i_] + (c_) * 64 + u_ * 8);                        \
    }                                                                         \
    _Pragma("unroll")                                                         \
    for (int i_ = 0; i_ < 8; i_++) {                                          \
        int f_ = i_ * 128 + tid;                                              \
        int r_ = f_ >> 3, u_ = us[i_];                                        \
        unsigned d_ = bb_ + r_ * 128 + ((u_ ^ (r_ & 7)) << 4);                \
        CP_ASYNC16(d_, brow[i_] + (c_) * 64 + u_ * 8);                        \
    }                                                                         \
    asm volatile("cp.async.commit_group;" ::: "memory");                      \
} while (0)

    float acc[4][8][4];
#pragma unroll
    for (int i = 0; i < 4; i++)
#pragma unroll
        for (int jn = 0; jn < 8; jn++)
#pragma unroll
            for (int k = 0; k < 4; k++) acc[i][jn][k] = 0.f;

    XG_ISSUE(0, 0);
    XG_ISSUE(1, 1);
    XG_ISSUE(2, 2);

    const int a_row0 = m_w + ((lane >> 3) & 1) * 8 + (lane & 7);
    const int a_usel = lane >> 4;
    const int b_row0 = n_w + (lane & 7);
    const int b_usel = lane >> 3;

#pragma unroll
    for (int c = 0; c < 4; c++) {
        if (c == 0 || c == 1) asm volatile("cp.async.wait_group 2;" ::: "memory");
        else if (c == 2)      asm volatile("cp.async.wait_group 1;" ::: "memory");
        else                  asm volatile("cp.async.wait_group 0;" ::: "memory");
        __syncthreads();

        unsigned ab = sb + (c % 3) * LT_STAGE;
        unsigned bb = ab + LT_A_BYTES;

        unsigned bf[8][4];
#pragma unroll
        for (int ks = 0; ks < 4; ks++) {
            if ((ks & 1) == 0) {
                const int p = ks >> 1;
#pragma unroll
                for (int ni = 0; ni < 8; ni++) {
                    int row = b_row0 + ni * 8;
                    int u = 4 * p + b_usel;
                    unsigned addr = bb + row * 128 + ((u ^ (row & 7)) << 4);
                    LDSM_X4(bf[ni][0], bf[ni][1], bf[ni][2], bf[ni][3], addr);
                }
            }
            unsigned af[4][4];
#pragma unroll
            for (int mi = 0; mi < 4; mi++) {
                int row = a_row0 + mi * 16;
                int u = 2 * ks + a_usel;
                unsigned addr = ab + row * 128 + ((u ^ (row & 7)) << 4);
                LDSM_X4(af[mi][0], af[mi][1], af[mi][2], af[mi][3], addr);
            }
            const int h = (ks & 1) * 2;
#pragma unroll
            for (int mi = 0; mi < 4; mi++)
#pragma unroll
                for (int ni = 0; ni < 8; ni++)
                    mma_f16(acc[mi][ni], af[mi][0], af[mi][1], af[mi][2], af[mi][3],
                            bf[ni][h], bf[ni][h + 1]);
        }
        __syncthreads();
        if (c == 0) XG_ISSUE(3, 0);
    }

    float* xout = enc ? (g_xg_enc + (long)m_blk * G_SZ)
                      : (g_xg_dec + (long)(m_blk - M_ENC) * G_SZ);
#pragma unroll
    for (int mi = 0; mi < 4; mi++) {
        int rm0 = m_w + mi * 16 + group;
#pragma unroll
        for (int ni = 0; ni < 8; ni++) {
            int gn = n_blk + n_w + ni * 8 + tig * 2;
            float2 bbv = *(const float2*)(bias + gn);
            float2 o0, o1;
            o0.x = acc[mi][ni][0] + bbv.x; o0.y = acc[mi][ni][1] + bbv.y;
            o1.x = acc[mi][ni][2] + bbv.x; o1.y = acc[mi][ni][3] + bbv.y;
            *(float2*)(xout + (long)rm0 * G_SZ + gn)       = o0;
            *(float2*)(xout + (long)(rm0 + 8) * G_SZ + gn) = o1;
        }
    }
#undef XG_ISSUE
}

// ---------------- kernel 2: cluster GRU v7c (R14 + xg prefetch hoist) ------
__global__ void __launch_bounds__(256, 1)
__cluster_dims__(GR_RANKS, 1, 1)
gru_rec(const float* __restrict__ encWhh, const float* __restrict__ encBhh,
        const float* __restrict__ decWhh, const float* __restrict__ decBhh)
{
    extern __shared__ __align__(16) float wn_s[];    // [64][257]
    __shared__ __align__(16) float h_s[2 * 512];     // [buf][k][b]
    __shared__ __align__(16) float redm[64 * 25];    // [ch][g*8 + b*4 + ksl]
    __shared__ __align__(16) unsigned long long h_mb[2];

    const int tid  = threadIdx.x;
    const int j    = tid & 63;   // channel within CTA
    const int ksl  = tid >> 6;   // k-slice (64 k each)
    const int rank = blockIdx.x & (GR_RANKS - 1);
    const int cid  = blockIdx.x >> 2;

    for (int i = tid; i < 1024; i += 256) h_s[i] = 0.f;
    if (tid == 0) {
        MBAR_INIT(smem_u32(&h_mb[0]), 1);
        MBAR_INIT(smem_u32(&h_mb[1]), 1);
        MBAR_EXPECT(smem_u32(&h_mb[0]), 2048u);
        MBAR_EXPECT(smem_u32(&h_mb[1]), 2048u);
    }
    __syncthreads();
    asm volatile("barrier.cluster.arrive.aligned;" ::: "memory");
    asm volatile("barrier.cluster.wait.aligned;" ::: "memory");

    const bool is_red = (tid < 64);
    const int cg  = rank * 64 + j;
    const unsigned h_base = smem_u32(h_s);
    const unsigned mb_base = smem_u32(&h_mb[0]);

    int buf = 0;
    int par0 = 0, par1 = 0;
    bool first = true;
    for (int ph = 0; ph < 2; ph++) {
        const int T = ph ? T_DEC : T_ENC;
        const float* xg  = ph ? g_xg_dec : g_xg_enc;
        const float* Bhh = ph ? decBhh : encBhh;
        const float* Wp  = ph ? decWhh : encWhh;

        float wr[64], wz[64];
        {
            const float* pr = Wp + (long)(0 * H_SZ + rank * 64 + j) * H_SZ + ksl * 64;
            const float* pz = Wp + (long)(1 * H_SZ + rank * 64 + j) * H_SZ + ksl * 64;
#pragma unroll
            for (int q = 0; q < 16; q++) {
                float4 a = __ldg((const float4*)(pr + q * 4));
                wr[q*4+0]=a.x; wr[q*4+1]=a.y; wr[q*4+2]=a.z; wr[q*4+3]=a.w;
                float4 b = __ldg((const float4*)(pz + q * 4));
                wz[q*4+0]=b.x; wz[q*4+1]=b.y; wz[q*4+2]=b.z; wz[q*4+3]=b.w;
            }
        }
        for (int fid = tid; fid < 64 * 64; fid += 256) {
            int q = fid & 63;
            int ch = fid >> 6;
            float4 v = __ldg((const float4*)(Wp + (long)(2 * H_SZ + rank * 64 + ch) * H_SZ + q * 4));
            float* dst = wn_s + ch * 257 + q * 4;
            dst[0] = v.x; dst[1] = v.y; dst[2] = v.z; dst[3] = v.w;
        }
        float br = 0.f, bz = 0.f, bn = 0.f;
        if (is_red) {
            br = __ldg(Bhh + cg);
            bz = __ldg(Bhh + H_SZ + cg);
            bn = __ldg(Bhh + 2 * H_SZ + cg);
        }
        __syncthreads();

        const float* wn = wn_s + j * 257 + ksl * 64;

        for (int t = 0; t < T; t++) {
            // xg prefetch BEFORE the exchange wait (h-independent; hides gmem lat)
            float xr[2], xz[2], xn[2];
            if (is_red) {
#pragma unroll
                for (int b = 0; b < 2; b++) {
                    const int bg = cid * GR_BPC + b;
                    const float* xp = xg + (long)(bg * T + t) * G_SZ + cg;
                    xr[b] = __ldg(xp); xz[b] = __ldg(xp + H_SZ); xn[b] = __ldg(xp + 2 * H_SZ);
                }
            }

            if (!first) {
                unsigned mb = mb_base + buf * 8;
                int par = buf ? par1 : par0;
                MBAR_WAIT(mb, par);
                if (buf) par1 ^= 1; else par0 ^= 1;
                if (tid == 0) MBAR_EXPECT(mb, 2048u);
            }
            first = false;

            // fma2 packed dot over this thread's 64-k slice (both batches)
            unsigned long long a0 = 0ull, a1 = 0ull, a2 = 0ull;
            const float* hb = h_s + buf * 512 + ksl * 128;
#pragma unroll
            for (int kk = 0; kk < 64; kk++) {
                unsigned long long hv = *(const unsigned long long*)(hb + kk * 2);
                fma2(a0, hv, dup2(wr[kk]));
                fma2(a1, hv, dup2(wz[kk]));
                fma2(a2, hv, dup2(wn[kk]));
            }
            {
                float p0, p1;
                float* rp = redm + j * 25;
                unpack2(a0, p0, p1);
                rp[0 * 8 + 0 + ksl] = p0; rp[0 * 8 + 4 + ksl] = p1;
                unpack2(a1, p0, p1);
                rp[1 * 8 + 0 + ksl] = p0; rp[1 * 8 + 4 + ksl] = p1;
                unpack2(a2, p0, p1);
                rp[2 * 8 + 0 + ksl] = p0; rp[2 * 8 + 4 + ksl] = p1;
            }
            __syncthreads();

            if (is_red) {
                float hnew[2];
#pragma unroll
                for (int b = 0; b < 2; b++) {
                    float s[3];
#pragma unroll
                    for (int g = 0; g < 3; g++) {
                        const float* rp = redm + j * 25 + g * 8 + b * 4;
                        s[g] = (rp[0] + rp[1]) + (rp[2] + rp[3]);
                    }
                    float hold = h_s[buf * 512 + cg * 2 + b];
                    float r = 1.f / (1.f + __expf(-(xr[b] + s[0] + br)));
                    float z = 1.f / (1.f + __expf(-(xz[b] + s[1] + bz)));
                    float n = tanhf(xn[b] + r * (s[2] + bn));
                    hnew[b] = (1.f - z) * n + z * hold;
                }

                const int nb = buf ^ 1;
                unsigned long long hp = pack64(hnew[0], hnew[1]);
                unsigned laddr = h_base + (unsigned)((nb * 512 + cg * 2) * 4);
                unsigned lmb   = mb_base + nb * 8;
#pragma unroll
                for (int rr = 0; rr < GR_RANKS; rr++) {
                    unsigned ra, rm;
                    asm volatile("mapa.shared::cluster.u32 %0, %1, %2;"
                                 : "=r"(ra) : "r"(laddr), "r"(rr));
                    asm volatile("mapa.shared::cluster.u32 %0, %1, %2;"
                                 : "=r"(rm) : "r"(lmb), "r"(rr));
                    asm volatile(
                        "st.async.shared::cluster.mbarrier::complete_tx::bytes.b64 [%0], %1, [%2];"
                        :: "r"(ra), "l"(hp), "r"(rm) : "memory");
                }
                if (ph) {
#pragma unroll
                    for (int b = 0; b < 2; b++) {
                        const int bg = cid * GR_BPC + b;
                        g_dech_h[(long)(bg * T_DEC + t) * H_SZ + cg] = f2h(hnew[b]);
                    }
                }
            }
            buf ^= 1;
        }
        __syncthreads();
    }
    {
        unsigned mb = mb_base + buf * 8;
        int par = buf ? par1 : par0;
        MBAR_WAIT(mb, par);
    }
    asm volatile("barrier.cluster.arrive.aligned;" ::: "memory");
    asm volatile("barrier.cluster.wait.aligned;" ::: "memory");
}

// ---------------- kernel 3: logits, pipelined frags, 3-stage cp.async ------
// Warp tile 64x64. A frags double-buffered, both B groups resident; LDSM for
// iteration ks+1 issued before the mma block of ks (hides LDSM latency).
__global__ void __launch_bounds__(128, 2) logits_f16(
    const float* __restrict__ fcb, float* __restrict__ out)
{
    extern __shared__ __align__(16) char smc[];
    const unsigned sb = smem_u32(smc);
    const int tid = threadIdx.x;
    const int warp = tid >> 5, lane = tid & 31;
    const int group = lane >> 2, tig = lane & 3;
    const int m_blk = blockIdx.x * 128;
    const int n_blk = blockIdx.y * 128;
    const int m_w = (warp >> 1) * 64;
    const int n_w = (warp & 1) * 64;

#define LT_ISSUE(c_, s_) do {                                                 \
    unsigned ab_ = sb + (s_) * LT_STAGE;                                      \
    unsigned bb_ = ab_ + LT_A_BYTES;                                          \
    _Pragma("unroll")                                                         \
    for (int i_ = 0; i_ < 8; i_++) {                                          \
        int f_ = i_ * 128 + tid;                                              \
        int r_ = f_ >> 3, u_ = f_ & 7;                                        \
        unsigned d_ = ab_ + r_ * 128 + ((u_ ^ (r_ & 7)) << 4);                \
        const void* s2_ = g_dech_h + (long)(m_blk + r_) * 256 + (c_) * 64 + u_ * 8; \
        CP_ASYNC16(d_, s2_);                                                  \
    }                                                                         \
    _Pragma("unroll")                                                         \
    for (int i_ = 0; i_ < 8; i_++) {                                          \
        int f_ = i_ * 128 + tid;                                              \
        int r_ = f_ >> 3, u_ = f_ & 7;                                        \
        unsigned d_ = bb_ + r_ * 128 + ((u_ ^ (r_ & 7)) << 4);                \
        const void* s2_ = g_fcw_h + (long)(n_blk + r_) * 256 + (c_) * 64 + u_ * 8; \
        CP_ASYNC16(d_, s2_);                                                  \
    }                                                                         \
    asm volatile("cp.async.commit_group;" ::: "memory");                      \
} while (0)

// load A frags for iteration ks into buffer dstb
#define LD_AF(dstb, ks_) do {                                                 \
    _Pragma("unroll")                                                         \
    for (int mi_ = 0; mi_ < 4; mi_++) {                                       \
        int row_ = a_row0 + mi_ * 16;                                         \
        int u_ = 2 * (ks_) + a_usel;                                          \
        unsigned ad_ = ab + row_ * 128 + ((u_ ^ (row_ & 7)) << 4);            \
        LDSM_X4(af[dstb][mi_][0], af[dstb][mi_][1],                           \
                af[dstb][mi_][2], af[dstb][mi_][3], ad_);                     \
    }                                                                         \
} while (0)

// load B frag group p into bfX
#define LD_BF(dst, p_) do {                                                   \
    _Pragma("unroll")                                                         \
    for (int ni_ = 0; ni_ < 8; ni_++) {                                       \
        int row_ = b_row0 + ni_ * 8;                                          \
        int u_ = 4 * (p_) + b_usel;                                           \
        unsigned ad_ = bb + row_ * 128 + ((u_ ^ (row_ & 7)) << 4);            \
        LDSM_X4(dst[ni_][0], dst[ni_][1], dst[ni_][2], dst[ni_][3], ad_);     \
    }                                                                         \
} while (0)

#define MMA_BLK(abuf, bbuf, h_) do {                                          \
    _Pragma("unroll")                                                         \
    for (int mi_ = 0; mi_ < 4; mi_++)                                         \
        _Pragma("unroll")                                                     \
        for (int ni_ = 0; ni_ < 8; ni_++)                                     \
            mma_f16(acc[mi_][ni_], af[abuf][mi_][0], af[abuf][mi_][1],        \
                    af[abuf][mi_][2], af[abuf][mi_][3],                       \
                    bbuf[ni_][h_], bbuf[ni_][h_ + 1]);                        \
} while (0)

    float acc[4][8][4];
#pragma unroll
    for (int i = 0; i < 4; i++)
#pragma unroll
        for (int jn = 0; jn < 8; jn++)
#pragma unroll
            for (int k = 0; k < 4; k++) acc[i][jn][k] = 0.f;

    LT_ISSUE(0, 0);
    LT_ISSUE(1, 1);
    LT_ISSUE(2, 2);

    const int a_row0 = m_w + ((lane >> 3) & 1) * 8 + (lane & 7);
    const int a_usel = lane >> 4;
    const int b_row0 = n_w + (lane & 7);
    const int b_usel = lane >> 3;

#pragma unroll
    for (int c = 0; c < 4; c++) {
        if (c == 0 || c == 1) asm volatile("cp.async.wait_group 2;" ::: "memory");
        else if (c == 2)      asm volatile("cp.async.wait_group 1;" ::: "memory");
        else                  asm volatile("cp.async.wait_group 0;" ::: "memory");
        __syncthreads();

        unsigned ab = sb + (c % 3) * LT_STAGE;
        unsigned bb = ab + LT_A_BYTES;

        unsigned af[2][4][4];
        unsigned bfA[8][4], bfB[8][4];

        // prologue: B group 0 + A frags for ks=0
        LD_BF(bfA, 0);
        LD_AF(0, 0);

        // ks=0: prefetch af(ks1) + B group 1, then mma
        LD_AF(1, 1);
        LD_BF(bfB, 1);
        MMA_BLK(0, bfA, 0);
        // ks=1: prefetch af(ks2), mma
        LD_AF(0, 2);
        MMA_BLK(1, bfA, 2);
        // ks=2: prefetch af(ks3), mma
        LD_AF(1, 3);
        MMA_BLK(0, bfB, 0);
        // ks=3: mma
        MMA_BLK(1, bfB, 2);

        __syncthreads();
        if (c == 0) LT_ISSUE(3, 0);
    }

#pragma unroll
    for (int mi = 0; mi < 4; mi++) {
        int gm0 = m_blk + m_w + mi * 16 + group;
#pragma unroll
        for (int ni = 0; ni < 8; ni++) {
            int gn = n_blk + n_w + ni * 8 + tig * 2;
            float2 bbv = *(const float2*)(fcb + gn);
            float2 o0, o1;
            o0.x = acc[mi][ni][0] + bbv.x; o0.y = acc[mi][ni][1] + bbv.y;
            o1.x = acc[mi][ni][2] + bbv.x; o1.y = acc[mi][ni][3] + bbv.y;
            *(float2*)(out + (long)gm0 * V_OUT + gn)       = o0;
            *(float2*)(out + (long)(gm0 + 8) * V_OUT + gn) = o1;
        }
    }
#undef LT_ISSUE
#undef LD_AF
#undef LD_BF
#undef MMA_BLK
}

// ---------------- launch ----------------
extern "C" void kernel_launch(void* const* d_in, const int* in_sizes, int n_in,
                              void* d_out, int out_size) {
    const int*   src     = (const int*)  d_in[0];
    const int*   trg     = (const int*)  d_in[1];
    const float* enc_emb = (const float*)d_in[2];
    const float* enc_Wih = (const float*)d_in[3];
    const float* enc_Whh = (const float*)d_in[4];
    const float* enc_bih = (const float*)d_in[5];
    const float* enc_bhh = (const float*)d_in[6];
    const float* dec_emb = (const float*)d_in[7];
    const float* dec_Wih = (const float*)d_in[8];
    const float* dec_Whh = (const float*)d_in[9];
    const float* dec_bih = (const float*)d_in[10];
    const float* dec_bhh = (const float*)d_in[11];
    const float* fc_W    = (const float*)d_in[12];
    const float* fc_b    = (const float*)d_in[13];
    float* out = (float*)d_out;

    static bool attr_done = false;
    if (!attr_done) {
        cudaFuncSetAttribute((const void*)gru_rec,
                             cudaFuncAttributeMaxDynamicSharedMemorySize,
                             GR_SMEM_BYTES);
        cudaFuncSetAttribute((const void*)logits_f16,
                             cudaFuncAttributeMaxDynamicSharedMemorySize,
                             LT_SMEM);
        cudaFuncSetAttribute((const void*)xg_f16,
                             cudaFuncAttributeMaxDynamicSharedMemorySize,
                             LT_SMEM);
        attr_done = true;
    }

    prep<<<PREP_BLKS, 256>>>(fc_W, enc_Wih, dec_Wih, enc_emb, dec_emb, src, trg);
    xg_f16<<<dim3(M_ALL / 128, G_SZ / 128), 128, LT_SMEM>>>(enc_bih, dec_bih);
    gru_rec<<<GR_CTAS, 256, GR_SMEM_BYTES>>>(enc_Whh, enc_bhh, dec_Whh, dec_bhh);
    logits_f16<<<dim3(M_DEC / 128, V_OUT / 128), 128, LT_SMEM>>>(fc_b, out);
}